// round 2
// baseline (speedup 1.0000x reference)
#include <cuda_runtime.h>
#include <cstdint>

// Problem constants
constexpr int NND = 100000;   // nodes
constexpr int DD  = 128;      // feature dim
constexpr int EE  = 250000;   // edges
constexpr int NRL = 16;       // relations
constexpr int RR  = 8;        // lora rank
constexpr int H   = 256;      // hidden (2*D)
constexpr int TE  = 64;       // edges per GEMM tile
constexpr int MAXTILES = 4096;

// Scratch (static device globals; no allocation at runtime)
__device__ float g_M[NRL * DD * DD];            // fused per-relation matrices M_t[i][o]
__device__ float g_out[(size_t)NND * DD];       // GIN pre-MLP accumulator
__device__ float g_h1[(size_t)NND * H];
__device__ float g_h2[(size_t)NND * H];
__device__ int   g_eids[EE];
__device__ int   g_cnt[NRL];
__device__ int   g_off[NRL + 1];
__device__ int   g_fill[NRL];
__device__ int   g_tiles[MAXTILES * 2];         // (type, edge_start) per tile; type=-1 unused

// ---------------------------------------------------------------------------
__global__ void k_clear() {
    int i = threadIdx.x;
    if (i < NRL) { g_cnt[i] = 0; g_fill[i] = 0; }
}

// M_t[i][o] = W[o,i] + sum_k B_t[i,k] * A_t[o,k]
__global__ void k_build_M(const float* __restrict__ W,
                          const float* __restrict__ A_emb,
                          const float* __restrict__ B_emb) {
    int t = blockIdx.x;
    __shared__ float As[DD * RR];
    __shared__ float Bs[DD * RR];
    for (int i = threadIdx.x; i < DD * RR; i += blockDim.x) {
        As[i] = A_emb[(size_t)t * DD * RR + i];
        Bs[i] = B_emb[(size_t)t * DD * RR + i];
    }
    __syncthreads();
    for (int idx = threadIdx.x; idx < DD * DD; idx += blockDim.x) {
        int i = idx >> 7;       // input dim
        int o = idx & 127;      // output dim
        float s = W[o * DD + i];
#pragma unroll
        for (int k = 0; k < RR; k++) s += Bs[i * RR + k] * As[o * RR + k];
        g_M[t * DD * DD + idx] = s;
    }
}

// g_out = (1+eps) * x
__global__ void k_init_out(const float* __restrict__ x, const float* __restrict__ eps) {
    float s = 1.0f + eps[0];
    int i = blockIdx.x * blockDim.x + threadIdx.x;
    int total = NND * DD / 4;
    if (i < total) {
        float4 v = ((const float4*)x)[i];
        v.x *= s; v.y *= s; v.z *= s; v.w *= s;
        ((float4*)g_out)[i] = v;
    }
}

__global__ void k_hist(const int* __restrict__ et) {
    __shared__ int lc[NRL];
    if (threadIdx.x < NRL) lc[threadIdx.x] = 0;
    __syncthreads();
    int e = blockIdx.x * blockDim.x + threadIdx.x;
    if (e < EE) {
        int t = et[e];
        if (t >= 0 && t < NRL) atomicAdd(&lc[t], 1);
    }
    __syncthreads();
    if (threadIdx.x < NRL && lc[threadIdx.x]) atomicAdd(&g_cnt[threadIdx.x], lc[threadIdx.x]);
}

__global__ void k_build_tiles() {
    __shared__ int off_s[NRL + 1], tbase[NRL + 1];
    if (threadIdx.x == 0) {
        int acc = 0;
        for (int t = 0; t < NRL; t++) { off_s[t] = acc; acc += g_cnt[t]; }
        off_s[NRL] = acc;
        int tb = 0;
        for (int t = 0; t < NRL; t++) { tbase[t] = tb; tb += (g_cnt[t] + TE - 1) / TE; }
        tbase[NRL] = tb;
        for (int t = 0; t <= NRL; t++) g_off[t] = off_s[t];
    }
    __syncthreads();
    for (int s = threadIdx.x; s < MAXTILES; s += blockDim.x) {
        int t = -1, e0 = 0;
        for (int tt = 0; tt < NRL; tt++) {
            if (s >= tbase[tt] && s < tbase[tt + 1]) {
                t = tt;
                e0 = off_s[tt] + (s - tbase[tt]) * TE;
            }
        }
        g_tiles[2 * s] = t;
        g_tiles[2 * s + 1] = e0;
    }
}

__global__ void k_scatter(const int* __restrict__ et) {
    __shared__ int lc[NRL], lbase[NRL], lfill[NRL];
    if (threadIdx.x < NRL) { lc[threadIdx.x] = 0; lfill[threadIdx.x] = 0; }
    __syncthreads();
    int e = blockIdx.x * blockDim.x + threadIdx.x;
    int t = -1;
    if (e < EE) {
        t = et[e];
        if (t >= 0 && t < NRL) atomicAdd(&lc[t], 1); else t = -1;
    }
    __syncthreads();
    if (threadIdx.x < NRL && lc[threadIdx.x])
        lbase[threadIdx.x] = atomicAdd(&g_fill[threadIdx.x], lc[threadIdx.x]);
    __syncthreads();
    if (t >= 0) {
        int p = atomicAdd(&lfill[t], 1);
        g_eids[g_off[t] + lbase[t] + p] = e;
    }
}

// ---------------------------------------------------------------------------
// Edge GEMM: per tile of <=64 same-relation edges, msg[64,128] = Xgather @ M_t,
// then red.global.add.v4.f32 scatter into g_out[dst].
constexpr int XS_STRIDE = 132;  // padded row stride (bank-conflict avoidance)
constexpr int EDGE_SMEM = DD * DD * 4 + TE * XS_STRIDE * 4 + TE * 2 * 4;

__global__ void __launch_bounds__(256) k_edge_gemm(const float* __restrict__ x,
                                                   const int* __restrict__ ei) {
    extern __shared__ float sm[];
    float* Ms = sm;                         // 128*128
    float* Xs = sm + DD * DD;               // 64*132
    int* dsts = (int*)(Xs + TE * XS_STRIDE);
    int* srcs = dsts + TE;

    int bid = blockIdx.x;
    int t = g_tiles[2 * bid];
    if (t < 0) return;
    int e0 = g_tiles[2 * bid + 1];
    int cnt = g_off[t + 1] - e0;
    if (cnt > TE) cnt = TE;
    int tid = threadIdx.x;

    if (tid < TE) {
        int s = -1, d = -1;
        if (tid < cnt) {
            int e = g_eids[e0 + tid];
            s = ei[e];            // src row (int32 indices, [2,E] layout)
            d = ei[EE + e];       // dst row
            if (s < 0 || s >= NND) s = -1;
            if (d < 0 || d >= NND) d = -1;
        }
        srcs[tid] = s;
        dsts[tid] = d;
    }
    __syncthreads();

    // load M_t (64KB) cooperatively
    const float4* Msrc = (const float4*)(g_M + t * DD * DD);
    float4* Mdst = (float4*)Ms;
#pragma unroll
    for (int j = 0; j < 16; j++) Mdst[tid + j * 256] = Msrc[tid + j * 256];

    // gather 64 x-rows (padded with zeros)
#pragma unroll
    for (int j = 0; j < 8; j++) {
        int slot = tid + j * 256;            // 2048 float4 slots
        int row = slot >> 5, c = slot & 31;
        int s = srcs[row];
        float4 v = make_float4(0.f, 0.f, 0.f, 0.f);
        if (s >= 0) v = ((const float4*)(x + (size_t)s * DD))[c];
        *(float4*)&Xs[row * XS_STRIDE + c * 4] = v;
    }
    __syncthreads();

    int tx = tid & 15;       // output group: o = tx*8 .. +7
    int ty = tid >> 4;       // edge group:   e = ty*4 .. +3
    int xb = ty * 4;

    float acc[4][8];
#pragma unroll
    for (int i = 0; i < 4; i++)
#pragma unroll
        for (int j = 0; j < 8; j++) acc[i][j] = 0.f;

#pragma unroll 4
    for (int k4 = 0; k4 < DD; k4 += 4) {
        float av[4][4];
#pragma unroll
        for (int i = 0; i < 4; i++) {
            float4 a = *(const float4*)&Xs[(xb + i) * XS_STRIDE + k4];
            av[i][0] = a.x; av[i][1] = a.y; av[i][2] = a.z; av[i][3] = a.w;
        }
#pragma unroll
        for (int kk = 0; kk < 4; kk++) {
            float4 b0 = *(const float4*)&Ms[(k4 + kk) * DD + tx * 8];
            float4 b1 = *(const float4*)&Ms[(k4 + kk) * DD + tx * 8 + 4];
            float bb[8] = {b0.x, b0.y, b0.z, b0.w, b1.x, b1.y, b1.z, b1.w};
#pragma unroll
            for (int i = 0; i < 4; i++)
#pragma unroll
                for (int j = 0; j < 8; j++) acc[i][j] += av[i][kk] * bb[j];
        }
    }

    // scatter-add to g_out[dst]
#pragma unroll
    for (int i = 0; i < 4; i++) {
        int d = dsts[xb + i];
        if (d < 0) continue;
        float* p = g_out + (size_t)d * DD + tx * 8;
        asm volatile("red.global.add.v4.f32 [%0], {%1,%2,%3,%4};"
                     :: "l"(p), "f"(acc[i][0]), "f"(acc[i][1]), "f"(acc[i][2]), "f"(acc[i][3])
                     : "memory");
        asm volatile("red.global.add.v4.f32 [%0], {%1,%2,%3,%4};"
                     :: "l"(p + 4), "f"(acc[i][4]), "f"(acc[i][5]), "f"(acc[i][6]), "f"(acc[i][7])
                     : "memory");
    }
}

// ---------------------------------------------------------------------------
// MLP GEMM: Out[r,o] = act(sum_k In[r,k]*Wt[o,k] + bias[o]).
// 128x128 block tile, BK=8, 256 threads, 8x8 per-thread tile.
template <bool RELU>
__global__ void __launch_bounds__(256) mlp_gemm(const float* __restrict__ In,
                                                const float* __restrict__ Wt,
                                                const float* __restrict__ bias,
                                                float* __restrict__ Out,
                                                int Nrows, int K, int O) {
    __shared__ float As[8][128];
    __shared__ float Bs[8][128];
    int tid = threadIdx.x;
    int row0 = blockIdx.x * 128;
    int col0 = blockIdx.y * 128;
    int tx = tid & 15, ty = tid >> 4;
    int r0 = ty * 8, c0 = tx * 8;

    float acc[8][8];
#pragma unroll
    for (int i = 0; i < 8; i++)
#pragma unroll
        for (int j = 0; j < 8; j++) acc[i][j] = 0.f;

    int lr = tid >> 1;          // 0..127
    int lk = (tid & 1) * 4;     // 0 or 4

    for (int k0 = 0; k0 < K; k0 += 8) {
        float4 av = make_float4(0.f, 0.f, 0.f, 0.f);
        int gr = row0 + lr;
        if (gr < Nrows) av = *(const float4*)&In[(size_t)gr * K + k0 + lk];
        As[lk + 0][lr] = av.x; As[lk + 1][lr] = av.y;
        As[lk + 2][lr] = av.z; As[lk + 3][lr] = av.w;

        float4 bv = *(const float4*)&Wt[(size_t)(col0 + lr) * K + k0 + lk];
        Bs[lk + 0][lr] = bv.x; Bs[lk + 1][lr] = bv.y;
        Bs[lk + 2][lr] = bv.z; Bs[lk + 3][lr] = bv.w;
        __syncthreads();

#pragma unroll
        for (int k = 0; k < 8; k++) {
            float4 a0 = *(const float4*)&As[k][r0];
            float4 a1 = *(const float4*)&As[k][r0 + 4];
            float4 b0 = *(const float4*)&Bs[k][c0];
            float4 b1 = *(const float4*)&Bs[k][c0 + 4];
            float aa[8] = {a0.x, a0.y, a0.z, a0.w, a1.x, a1.y, a1.z, a1.w};
            float bb[8] = {b0.x, b0.y, b0.z, b0.w, b1.x, b1.y, b1.z, b1.w};
#pragma unroll
            for (int i = 0; i < 8; i++)
#pragma unroll
                for (int j = 0; j < 8; j++) acc[i][j] += aa[i] * bb[j];
        }
        __syncthreads();
    }

    float bvals[8];
#pragma unroll
    for (int j = 0; j < 8; j++) bvals[j] = bias[col0 + c0 + j];

#pragma unroll
    for (int i = 0; i < 8; i++) {
        int gr = row0 + r0 + i;
        if (gr < Nrows) {
#pragma unroll
            for (int j = 0; j < 8; j++) {
                float v = acc[i][j] + bvals[j];
                if (RELU) v = fmaxf(v, 0.f);
                acc[i][j] = v;
            }
            float4* p = (float4*)&Out[(size_t)gr * O + col0 + c0];
            p[0] = make_float4(acc[i][0], acc[i][1], acc[i][2], acc[i][3]);
            p[1] = make_float4(acc[i][4], acc[i][5], acc[i][6], acc[i][7]);
        }
    }
}

// ---------------------------------------------------------------------------
extern "C" void kernel_launch(void* const* d_in, const int* in_sizes, int n_in,
                              void* d_out, int out_size) {
    const float* x     = (const float*)d_in[0];
    const int*   ei    = (const int*)d_in[1];   // int32 [2,E] (JAX x64 disabled)
    const int*   et    = (const int*)d_in[2];   // int32 [E]
    const float* W     = (const float*)d_in[3];
    const float* eps   = (const float*)d_in[4];
    const float* A_emb = (const float*)d_in[5];
    const float* B_emb = (const float*)d_in[6];
    const float* W1    = (const float*)d_in[7];
    const float* b1    = (const float*)d_in[8];
    const float* W2    = (const float*)d_in[9];
    const float* b2    = (const float*)d_in[10];
    const float* W3    = (const float*)d_in[11];
    const float* b3    = (const float*)d_in[12];
    float* out = (float*)d_out;

    void *p_out_v, *p_h1_v, *p_h2_v;
    cudaGetSymbolAddress(&p_out_v, g_out);
    cudaGetSymbolAddress(&p_h1_v, g_h1);
    cudaGetSymbolAddress(&p_h2_v, g_h2);
    float* p_out = (float*)p_out_v;
    float* p_h1  = (float*)p_h1_v;
    float* p_h2  = (float*)p_h2_v;

    cudaFuncSetAttribute(k_edge_gemm, cudaFuncAttributeMaxDynamicSharedMemorySize, EDGE_SMEM);

    k_clear<<<1, 32>>>();
    k_build_M<<<NRL, 256>>>(W, A_emb, B_emb);
    k_init_out<<<(NND * DD / 4 + 255) / 256, 256>>>(x, eps);
    k_hist<<<(EE + 255) / 256, 256>>>(et);
    k_build_tiles<<<1, 256>>>();
    k_scatter<<<(EE + 255) / 256, 256>>>(et);
    k_edge_gemm<<<MAXTILES, 256, EDGE_SMEM>>>(x, ei);

    dim3 g12((NND + 127) / 128, H / 128);
    mlp_gemm<true><<<g12, 256>>>(p_out, W1, b1, p_h1, NND, DD, H);
    mlp_gemm<true><<<g12, 256>>>(p_h1, W2, b2, p_h2, NND, H, H);
    dim3 g3((NND + 127) / 128, DD / 128);
    mlp_gemm<false><<<g3, 256>>>(p_h2, W3, b3, out, NND, H, DD);
}

// round 3
// speedup vs baseline: 2.2374x; 2.2374x over previous
#include <cuda_runtime.h>
#include <cstdint>

constexpr int NND = 100000;
constexpr int DD  = 128;
constexpr int EE  = 250000;
constexpr int NRL = 16;
constexpr int RR  = 8;
constexpr int H   = 256;
constexpr int TE  = 64;
constexpr int MAXTILES = 4096;

// Static device scratch
__device__ float g_Mt[NRL * DD * DD];          // fused M^T per relation, tf32-rounded, [t][o][i]
__device__ float g_out[(size_t)NND * DD];      // GIN pre-MLP accumulator (fp32)
__device__ float g_h1[(size_t)NND * H];
__device__ float g_h2[(size_t)NND * H];
__device__ float g_W1r[H * DD];
__device__ float g_W2r[H * H];
__device__ float g_W3r[DD * H];
__device__ int   g_eids[EE];
__device__ int   g_cnt[NRL];
__device__ int   g_off[NRL + 1];
__device__ int   g_fill[NRL];
__device__ int   g_tiles[MAXTILES * 2];

// ---------------------------------------------------------------------------
__device__ __forceinline__ uint32_t f2tf(float f) {
    uint32_t u; asm("cvt.rna.tf32.f32 %0, %1;" : "=r"(u) : "f"(f)); return u;
}
__device__ __forceinline__ float f2tff(float f) { return __uint_as_float(f2tf(f)); }

__device__ __forceinline__ void ldsm4(uint32_t* r, uint32_t addr) {
    asm volatile("ldmatrix.sync.aligned.m8n8.x4.shared.b16 {%0,%1,%2,%3}, [%4];"
                 : "=r"(r[0]), "=r"(r[1]), "=r"(r[2]), "=r"(r[3]) : "r"(addr));
}
__device__ __forceinline__ void mma8(float* d, const uint32_t* a, uint32_t b0, uint32_t b1) {
    asm volatile(
        "mma.sync.aligned.m16n8k8.row.col.f32.tf32.tf32.f32 "
        "{%0,%1,%2,%3},{%4,%5,%6,%7},{%8,%9},{%0,%1,%2,%3};"
        : "+f"(d[0]), "+f"(d[1]), "+f"(d[2]), "+f"(d[3])
        : "r"(a[0]), "r"(a[1]), "r"(a[2]), "r"(a[3]), "r"(b0), "r"(b1));
}

// ---------------------------------------------------------------------------
__global__ void k_clear() {
    int i = threadIdx.x;
    if (i < NRL) { g_cnt[i] = 0; g_fill[i] = 0; }
}

// g_Mt[t][o][i] = W[o,i] + sum_k B_t[i,k] * A_t[o,k]   (tf32-rounded)
__global__ void k_build_M(const float* __restrict__ W,
                          const float* __restrict__ A_emb,
                          const float* __restrict__ B_emb) {
    int t = blockIdx.x;
    __shared__ float As[DD * RR];
    __shared__ float Bs[DD * RR];
    for (int i = threadIdx.x; i < DD * RR; i += blockDim.x) {
        As[i] = A_emb[(size_t)t * DD * RR + i];
        Bs[i] = B_emb[(size_t)t * DD * RR + i];
    }
    __syncthreads();
    for (int idx = threadIdx.x; idx < DD * DD; idx += blockDim.x) {
        int o = idx >> 7;
        int i = idx & 127;
        float s = W[o * DD + i];
#pragma unroll
        for (int k = 0; k < RR; k++) s += Bs[i * RR + k] * As[o * RR + k];
        g_Mt[t * DD * DD + o * DD + i] = f2tff(s);
    }
}

// round MLP weights to tf32 once
__global__ void k_round_w(const float* __restrict__ W1, const float* __restrict__ W2,
                          const float* __restrict__ W3) {
    int i = blockIdx.x * blockDim.x + threadIdx.x;
    if (i < H * DD) g_W1r[i] = f2tff(W1[i]);
    if (i < H * H)  g_W2r[i] = f2tff(W2[i]);
    if (i < DD * H) g_W3r[i] = f2tff(W3[i]);
}

__global__ void k_init_out(const float* __restrict__ x, const float* __restrict__ eps) {
    float s = 1.0f + eps[0];
    int i = blockIdx.x * blockDim.x + threadIdx.x;
    int total = NND * DD / 4;
    if (i < total) {
        float4 v = ((const float4*)x)[i];
        v.x *= s; v.y *= s; v.z *= s; v.w *= s;
        ((float4*)g_out)[i] = v;
    }
}

__global__ void k_hist(const int* __restrict__ et) {
    __shared__ int lc[NRL];
    if (threadIdx.x < NRL) lc[threadIdx.x] = 0;
    __syncthreads();
    int e = blockIdx.x * blockDim.x + threadIdx.x;
    if (e < EE) {
        int t = et[e];
        if (t >= 0 && t < NRL) atomicAdd(&lc[t], 1);
    }
    __syncthreads();
    if (threadIdx.x < NRL && lc[threadIdx.x]) atomicAdd(&g_cnt[threadIdx.x], lc[threadIdx.x]);
}

__global__ void k_build_tiles() {
    __shared__ int off_s[NRL + 1], tbase[NRL + 1];
    if (threadIdx.x == 0) {
        int acc = 0;
        for (int t = 0; t < NRL; t++) { off_s[t] = acc; acc += g_cnt[t]; }
        off_s[NRL] = acc;
        int tb = 0;
        for (int t = 0; t < NRL; t++) { tbase[t] = tb; tb += (g_cnt[t] + TE - 1) / TE; }
        tbase[NRL] = tb;
        for (int t = 0; t <= NRL; t++) g_off[t] = off_s[t];
    }
    __syncthreads();
    for (int s = threadIdx.x; s < MAXTILES; s += blockDim.x) {
        int t = -1, e0 = 0;
        for (int tt = 0; tt < NRL; tt++) {
            if (s >= tbase[tt] && s < tbase[tt + 1]) {
                t = tt;
                e0 = off_s[tt] + (s - tbase[tt]) * TE;
            }
        }
        g_tiles[2 * s] = t;
        g_tiles[2 * s + 1] = e0;
    }
}

__global__ void k_scatter(const int* __restrict__ et) {
    __shared__ int lc[NRL], lbase[NRL], lfill[NRL];
    if (threadIdx.x < NRL) { lc[threadIdx.x] = 0; lfill[threadIdx.x] = 0; }
    __syncthreads();
    int e = blockIdx.x * blockDim.x + threadIdx.x;
    int t = -1;
    if (e < EE) {
        t = et[e];
        if (t >= 0 && t < NRL) atomicAdd(&lc[t], 1); else t = -1;
    }
    __syncthreads();
    if (threadIdx.x < NRL && lc[threadIdx.x])
        lbase[threadIdx.x] = atomicAdd(&g_fill[threadIdx.x], lc[threadIdx.x]);
    __syncthreads();
    if (t >= 0) {
        int p = atomicAdd(&lfill[t], 1);
        g_eids[g_off[t] + lbase[t] + p] = e;
    }
}

// ---------------------------------------------------------------------------
// Edge GEMM via tf32 mma: msg[64,128] = Xgather(tf32) @ M_t, scatter red.v4.
constexpr int EMS_F = DD * DD;   // 16384 floats (M^T tile)
constexpr int EXS_F = TE * DD;   // 8192  (X tile)
constexpr int EOS_F = TE * 132;  // 8448  (output staging, padded stride)
constexpr int EDGE_SMEM = (EMS_F + EXS_F + EOS_F) * 4 + 2 * TE * 4;

__global__ void __launch_bounds__(256) k_edge_mma(const float* __restrict__ x,
                                                  const int* __restrict__ ei) {
    extern __shared__ float sm[];
    float* Ms = sm;
    float* Xs = sm + EMS_F;
    float* Os = Xs + EXS_F;
    int* srcs = (int*)(Os + EOS_F);
    int* dsts = srcs + TE;

    int t = g_tiles[2 * blockIdx.x];
    if (t < 0) return;
    int e0 = g_tiles[2 * blockIdx.x + 1];
    int cnt = g_off[t + 1] - e0;
    if (cnt > TE) cnt = TE;
    int tid = threadIdx.x;

    if (tid < TE) {
        int s = -1, d = -1;
        if (tid < cnt) {
            int e = g_eids[e0 + tid];
            s = ei[e];
            d = ei[EE + e];
            if (s < 0 || s >= NND) s = -1;
            if (d < 0 || d >= NND) d = -1;
        }
        srcs[tid] = s;
        dsts[tid] = d;
    }
    __syncthreads();

    // load M^T tile (already tf32) with xor swizzle of 16B units within a 128-float row
    const float4* Msrc = (const float4*)(g_Mt + t * EMS_F);
#pragma unroll
    for (int j = 0; j < 16; j++) {
        int l = tid + j * 256;          // 4096 float4
        int r = l >> 5, u = l & 31;
        float4 v = Msrc[l];
        *(float4*)&Ms[r * DD + ((u ^ (r & 7)) << 2)] = v;
    }
    // gather X rows, round to tf32, same swizzle
#pragma unroll
    for (int j = 0; j < 8; j++) {
        int l = tid + j * 256;          // 2048 float4
        int r = l >> 5, u = l & 31;
        int s = srcs[r];
        float4 v = make_float4(0.f, 0.f, 0.f, 0.f);
        if (s >= 0) v = ((const float4*)(x + (size_t)s * DD))[u];
        v.x = f2tff(v.x); v.y = f2tff(v.y); v.z = f2tff(v.z); v.w = f2tff(v.w);
        *(float4*)&Xs[r * DD + ((u ^ (r & 7)) << 2)] = v;
    }
    __syncthreads();

    int lane = tid & 31, w = tid >> 5;
    int wm = w & 1, wn = w >> 1;                 // 2 m-bands(32 edges) x 4 n-bands(32 cols)
    uint32_t xs_base = (uint32_t)__cvta_generic_to_shared(Xs);
    uint32_t ms_base = (uint32_t)__cvta_generic_to_shared(Ms);
    int arow0 = wm * 32 + (lane & 15);
    int brow0 = wn * 32 + (lane & 15);

    float d[2][4][4];
#pragma unroll
    for (int mi = 0; mi < 2; mi++)
#pragma unroll
        for (int ni = 0; ni < 4; ni++)
#pragma unroll
            for (int c = 0; c < 4; c++) d[mi][ni][c] = 0.f;

#pragma unroll
    for (int ks = 0; ks < 16; ks++) {
        int uu = ks * 2 + (lane >> 4);
        uint32_t a[2][4], b[2][4];
#pragma unroll
        for (int mi = 0; mi < 2; mi++) {
            int r = arow0 + mi * 16;
            ldsm4(a[mi], xs_base + (uint32_t)((r * DD + ((uu ^ (r & 7)) << 2)) * 4));
        }
#pragma unroll
        for (int pp = 0; pp < 2; pp++) {
            int r = brow0 + pp * 16;
            ldsm4(b[pp], ms_base + (uint32_t)((r * DD + ((uu ^ (r & 7)) << 2)) * 4));
        }
#pragma unroll
        for (int mi = 0; mi < 2; mi++)
#pragma unroll
            for (int ni = 0; ni < 4; ni++) {
                int pp = ni >> 1, o = ni & 1;
                mma8(d[mi][ni], a[mi], b[pp][o], b[pp][2 + o]);
            }
    }

    // stage fragments to smem, then scatter with red.v4
#pragma unroll
    for (int mi = 0; mi < 2; mi++)
#pragma unroll
        for (int ni = 0; ni < 4; ni++) {
            int er = wm * 32 + mi * 16 + (lane >> 2);
            int oc = wn * 32 + ni * 8 + (lane & 3) * 2;
            *(float2*)&Os[er * 132 + oc]       = make_float2(d[mi][ni][0], d[mi][ni][1]);
            *(float2*)&Os[(er + 8) * 132 + oc] = make_float2(d[mi][ni][2], d[mi][ni][3]);
        }
    __syncthreads();

    int tx = tid & 15, ty = tid >> 4, xb = ty * 4;
#pragma unroll
    for (int i = 0; i < 4; i++) {
        int dn = dsts[xb + i];
        if (dn < 0) continue;
        float* p = g_out + (size_t)dn * DD + tx * 8;
        const float* q = &Os[(xb + i) * 132 + tx * 8];
        asm volatile("red.global.add.v4.f32 [%0], {%1,%2,%3,%4};"
                     :: "l"(p), "f"(q[0]), "f"(q[1]), "f"(q[2]), "f"(q[3]) : "memory");
        asm volatile("red.global.add.v4.f32 [%0], {%1,%2,%3,%4};"
                     :: "l"(p + 4), "f"(q[4]), "f"(q[5]), "f"(q[6]), "f"(q[7]) : "memory");
    }
}

// ---------------------------------------------------------------------------
// MLP GEMM via tf32 mma: Out[r,o] = act(sum_k In[r,k]*Wt[o,k] + bias[o]).
// BM=128 BN=128 BK=32, 4-stage cp.async, 256 threads, warp tile 64x32.
constexpr int BM = 128, BN = 128, BK = 32, NSTG = 4;
constexpr int MLP_SMEM = NSTG * (BM * BK + BN * BK) * 4;   // 131072

template <bool RELU, bool ROUND, bool CVTA>
__global__ void __launch_bounds__(256) mlp_mma(const float* __restrict__ In,
                                               const float* __restrict__ Wt,
                                               const float* __restrict__ bias,
                                               float* __restrict__ Out,
                                               int Nrows, int K, int O) {
    extern __shared__ float sm[];
    float* Abuf = sm;                     // [NSTG][BM*BK]
    float* Bbuf = sm + NSTG * BM * BK;    // [NSTG][BN*BK]
    int tid = threadIdx.x, lane = tid & 31, w = tid >> 5;
    int row0 = blockIdx.x * BM, col0 = blockIdx.y * BN;
    int kt = K / BK;

    auto issue = [&](int s) {
        int buf = s & (NSTG - 1);
        uint32_t abase = (uint32_t)__cvta_generic_to_shared(Abuf + buf * BM * BK);
        uint32_t bbase = (uint32_t)__cvta_generic_to_shared(Bbuf + buf * BN * BK);
        int k0 = s * BK;
#pragma unroll
        for (int i = 0; i < 4; i++) {
            int l = tid + i * 256;
            int r = l >> 3, u = l & 7;
            int gr = row0 + r;
            bool pa = gr < Nrows;
            const float* srcA = pa ? (In + (size_t)gr * K + k0 + u * 4) : In;
            uint32_t da = abase + (uint32_t)((r * BK + ((u ^ (r & 7)) << 2)) * 4);
            asm volatile("cp.async.ca.shared.global [%0], [%1], 16, %2;"
                         :: "r"(da), "l"(srcA), "r"(pa ? 16 : 0));
            const float* srcB = Wt + (size_t)(col0 + r) * K + k0 + u * 4;
            uint32_t db = bbase + (uint32_t)((r * BK + ((u ^ (r & 7)) << 2)) * 4);
            asm volatile("cp.async.ca.shared.global [%0], [%1], 16, %2;"
                         :: "r"(db), "l"(srcB), "r"(16));
        }
    };

    int wm = w & 1, wn = w >> 1;          // 2 m-warps x 4 n-warps -> warp tile 64x32
    int arow0 = wm * 64 + (lane & 15);
    int brow0 = wn * 32 + (lane & 15);

    float d[4][4][4];
#pragma unroll
    for (int mi = 0; mi < 4; mi++)
#pragma unroll
        for (int ni = 0; ni < 4; ni++)
#pragma unroll
            for (int c = 0; c < 4; c++) d[mi][ni][c] = 0.f;

    // prologue: always 3 committed groups (possibly empty) to keep counts in lockstep
    issue(0);               asm volatile("cp.async.commit_group;");
    if (kt > 1) issue(1);   asm volatile("cp.async.commit_group;");
    if (kt > 2) issue(2);   asm volatile("cp.async.commit_group;");

    for (int s = 0; s < kt; s++) {
        asm volatile("cp.async.wait_group %0;" :: "n"(2));
        __syncthreads();
        int buf = s & (NSTG - 1);
        uint32_t abase = (uint32_t)__cvta_generic_to_shared(Abuf + buf * BM * BK);
        uint32_t bbase = (uint32_t)__cvta_generic_to_shared(Bbuf + buf * BN * BK);

#pragma unroll
        for (int ks = 0; ks < 4; ks++) {
            int uu = ks * 2 + (lane >> 4);
            uint32_t a[4][4], b[2][4];
#pragma unroll
            for (int mi = 0; mi < 4; mi++) {
                int r = arow0 + mi * 16;
                ldsm4(a[mi], abase + (uint32_t)((r * BK + ((uu ^ (r & 7)) << 2)) * 4));
            }
            if (CVTA) {
#pragma unroll
                for (int mi = 0; mi < 4; mi++)
#pragma unroll
                    for (int j = 0; j < 4; j++)
                        a[mi][j] = f2tf(__uint_as_float(a[mi][j]));
            }
#pragma unroll
            for (int pp = 0; pp < 2; pp++) {
                int r = brow0 + pp * 16;
                ldsm4(b[pp], bbase + (uint32_t)((r * BK + ((uu ^ (r & 7)) << 2)) * 4));
            }
#pragma unroll
            for (int mi = 0; mi < 4; mi++)
#pragma unroll
                for (int ni = 0; ni < 4; ni++) {
                    int pp = ni >> 1, o = ni & 1;
                    mma8(d[mi][ni], a[mi], b[pp][o], b[pp][2 + o]);
                }
        }
        if (s + 3 < kt) issue(s + 3);
        asm volatile("cp.async.commit_group;");
    }

    // epilogue: bias (+relu) (+tf32 round), guarded float2 stores
#pragma unroll
    for (int ni = 0; ni < 4; ni++) {
        int gc = col0 + wn * 32 + ni * 8 + (lane & 3) * 2;
        float bj0 = bias[gc], bj1 = bias[gc + 1];
#pragma unroll
        for (int mi = 0; mi < 4; mi++) {
            int gr = row0 + wm * 64 + mi * 16 + (lane >> 2);
            float v0 = d[mi][ni][0] + bj0, v1 = d[mi][ni][1] + bj1;
            float v2 = d[mi][ni][2] + bj0, v3 = d[mi][ni][3] + bj1;
            if (RELU) {
                v0 = fmaxf(v0, 0.f); v1 = fmaxf(v1, 0.f);
                v2 = fmaxf(v2, 0.f); v3 = fmaxf(v3, 0.f);
            }
            if (ROUND) {
                v0 = f2tff(v0); v1 = f2tff(v1); v2 = f2tff(v2); v3 = f2tff(v3);
            }
            if (gr < Nrows)     *(float2*)&Out[(size_t)gr * O + gc]       = make_float2(v0, v1);
            if (gr + 8 < Nrows) *(float2*)&Out[(size_t)(gr + 8) * O + gc] = make_float2(v2, v3);
        }
    }
}

// ---------------------------------------------------------------------------
extern "C" void kernel_launch(void* const* d_in, const int* in_sizes, int n_in,
                              void* d_out, int out_size) {
    const float* x     = (const float*)d_in[0];
    const int*   ei    = (const int*)d_in[1];
    const int*   et    = (const int*)d_in[2];
    const float* W     = (const float*)d_in[3];
    const float* eps   = (const float*)d_in[4];
    const float* A_emb = (const float*)d_in[5];
    const float* B_emb = (const float*)d_in[6];
    const float* W1    = (const float*)d_in[7];
    const float* b1    = (const float*)d_in[8];
    const float* W2    = (const float*)d_in[9];
    const float* b2    = (const float*)d_in[10];
    const float* W3    = (const float*)d_in[11];
    const float* b3    = (const float*)d_in[12];
    float* out = (float*)d_out;

    void *p_out_v, *p_h1_v, *p_h2_v, *p_w1_v, *p_w2_v, *p_w3_v;
    cudaGetSymbolAddress(&p_out_v, g_out);
    cudaGetSymbolAddress(&p_h1_v, g_h1);
    cudaGetSymbolAddress(&p_h2_v, g_h2);
    cudaGetSymbolAddress(&p_w1_v, g_W1r);
    cudaGetSymbolAddress(&p_w2_v, g_W2r);
    cudaGetSymbolAddress(&p_w3_v, g_W3r);
    float* p_out = (float*)p_out_v;
    float* p_h1  = (float*)p_h1_v;
    float* p_h2  = (float*)p_h2_v;

    cudaFuncSetAttribute(k_edge_mma, cudaFuncAttributeMaxDynamicSharedMemorySize, EDGE_SMEM);
    cudaFuncSetAttribute(mlp_mma<true, true, true>,   cudaFuncAttributeMaxDynamicSharedMemorySize, MLP_SMEM);
    cudaFuncSetAttribute(mlp_mma<true, true, false>,  cudaFuncAttributeMaxDynamicSharedMemorySize, MLP_SMEM);
    cudaFuncSetAttribute(mlp_mma<false, false, false>,cudaFuncAttributeMaxDynamicSharedMemorySize, MLP_SMEM);

    k_clear<<<1, 32>>>();
    k_build_M<<<NRL, 256>>>(W, A_emb, B_emb);
    k_round_w<<<(H * H + 255) / 256, 256>>>(W1, W2, W3);
    k_init_out<<<(NND * DD / 4 + 255) / 256, 256>>>(x, eps);
    k_hist<<<(EE + 255) / 256, 256>>>(et);
    k_build_tiles<<<1, 256>>>();
    k_scatter<<<(EE + 255) / 256, 256>>>(et);
    k_edge_mma<<<MAXTILES, 256, EDGE_SMEM>>>(x, ei);

    int gx = (NND + BM - 1) / BM;   // 782
    dim3 g12(gx, H / BN);           // (782, 2)
    mlp_mma<true, true, true><<<g12, 256, MLP_SMEM>>>(p_out, (const float*)p_w1_v, b1, p_h1, NND, DD, H);
    mlp_mma<true, true, false><<<g12, 256, MLP_SMEM>>>(p_h1, (const float*)p_w2_v, b2, p_h2, NND, H, H);
    dim3 g3(gx, DD / BN);           // (782, 1)
    mlp_mma<false, false, false><<<g3, 256, MLP_SMEM>>>(p_h2, (const float*)p_w3_v, b3, out, NND, H, DD);
}

// round 4
// speedup vs baseline: 2.8650x; 1.2805x over previous
#include <cuda_runtime.h>
#include <cstdint>

constexpr int NND = 100000;
constexpr int DD  = 128;
constexpr int EE  = 250000;
constexpr int NRL = 16;
constexpr int RR  = 8;
constexpr int H   = 256;
constexpr int TE  = 64;
constexpr int MAXTILES = 4096;

// Static device scratch
__device__ float g_Mt[NRL * DD * DD];          // fused M^T per relation, tf32-rounded, [t][o][i]
__device__ float g_out[(size_t)NND * DD];      // GIN pre-MLP accumulator (fp32)
__device__ float g_h1[(size_t)NND * H];
__device__ float g_h2[(size_t)NND * H];
__device__ float g_W1r[H * DD];
__device__ float g_W2r[H * H];
__device__ float g_W3r[DD * H];
__device__ int   g_eids[EE];
__device__ int   g_cnt[NRL];
__device__ int   g_off[NRL + 1];
__device__ int   g_fill[NRL];
__device__ int   g_tiles[MAXTILES * 2];

// ---------------------------------------------------------------------------
__device__ __forceinline__ uint32_t f2tf(float f) {
    uint32_t u; asm("cvt.rna.tf32.f32 %0, %1;" : "=r"(u) : "f"(f)); return u;
}
__device__ __forceinline__ float f2tff(float f) { return __uint_as_float(f2tf(f)); }

__device__ __forceinline__ void ldsm4(uint32_t* r, uint32_t addr) {
    asm volatile("ldmatrix.sync.aligned.m8n8.x4.shared.b16 {%0,%1,%2,%3}, [%4];"
                 : "=r"(r[0]), "=r"(r[1]), "=r"(r[2]), "=r"(r[3]) : "r"(addr));
}
__device__ __forceinline__ void mma8(float* d, const uint32_t* a, uint32_t b0, uint32_t b1) {
    asm volatile(
        "mma.sync.aligned.m16n8k8.row.col.f32.tf32.tf32.f32 "
        "{%0,%1,%2,%3},{%4,%5,%6,%7},{%8,%9},{%0,%1,%2,%3};"
        : "+f"(d[0]), "+f"(d[1]), "+f"(d[2]), "+f"(d[3])
        : "r"(a[0]), "r"(a[1]), "r"(a[2]), "r"(a[3]), "r"(b0), "r"(b1));
}

// ---------------------------------------------------------------------------
__global__ void k_clear() {
    int i = threadIdx.x;
    if (i < NRL) { g_cnt[i] = 0; g_fill[i] = 0; }
}

// g_Mt[t][o][i] = W[o,i] + sum_k B_t[i,k] * A_t[o,k]   (tf32-rounded)
__global__ void k_build_M(const float* __restrict__ W,
                          const float* __restrict__ A_emb,
                          const float* __restrict__ B_emb) {
    int t = blockIdx.x;
    __shared__ float As[DD * RR];
    __shared__ float Bs[DD * RR];
    for (int i = threadIdx.x; i < DD * RR; i += blockDim.x) {
        As[i] = A_emb[(size_t)t * DD * RR + i];
        Bs[i] = B_emb[(size_t)t * DD * RR + i];
    }
    __syncthreads();
    for (int idx = threadIdx.x; idx < DD * DD; idx += blockDim.x) {
        int o = idx >> 7;
        int i = idx & 127;
        float s = W[o * DD + i];
#pragma unroll
        for (int k = 0; k < RR; k++) s += Bs[i * RR + k] * As[o * RR + k];
        g_Mt[t * DD * DD + o * DD + i] = f2tff(s);
    }
}

// round MLP weights to tf32 once
__global__ void k_round_w(const float* __restrict__ W1, const float* __restrict__ W2,
                          const float* __restrict__ W3) {
    int i = blockIdx.x * blockDim.x + threadIdx.x;
    if (i < H * DD) g_W1r[i] = f2tff(W1[i]);
    if (i < H * H)  g_W2r[i] = f2tff(W2[i]);
    if (i < DD * H) g_W3r[i] = f2tff(W3[i]);
}

__global__ void k_init_out(const float* __restrict__ x, const float* __restrict__ eps) {
    float s = 1.0f + eps[0];
    int i = blockIdx.x * blockDim.x + threadIdx.x;
    int total = NND * DD / 4;
    if (i < total) {
        float4 v = ((const float4*)x)[i];
        v.x *= s; v.y *= s; v.z *= s; v.w *= s;
        ((float4*)g_out)[i] = v;
    }
}

__global__ void k_hist(const int* __restrict__ et) {
    __shared__ int lc[NRL];
    if (threadIdx.x < NRL) lc[threadIdx.x] = 0;
    __syncthreads();
    int e = blockIdx.x * blockDim.x + threadIdx.x;
    if (e < EE) {
        int t = et[e];
        if (t >= 0 && t < NRL) atomicAdd(&lc[t], 1);
    }
    __syncthreads();
    if (threadIdx.x < NRL && lc[threadIdx.x]) atomicAdd(&g_cnt[threadIdx.x], lc[threadIdx.x]);
}

__global__ void k_build_tiles() {
    __shared__ int off_s[NRL + 1], tbase[NRL + 1];
    if (threadIdx.x == 0) {
        int acc = 0;
        for (int t = 0; t < NRL; t++) { off_s[t] = acc; acc += g_cnt[t]; }
        off_s[NRL] = acc;
        int tb = 0;
        for (int t = 0; t < NRL; t++) { tbase[t] = tb; tb += (g_cnt[t] + TE - 1) / TE; }
        tbase[NRL] = tb;
        for (int t = 0; t <= NRL; t++) g_off[t] = off_s[t];
    }
    __syncthreads();
    for (int s = threadIdx.x; s < MAXTILES; s += blockDim.x) {
        int t = -1, e0 = 0;
        for (int tt = 0; tt < NRL; tt++) {
            if (s >= tbase[tt] && s < tbase[tt + 1]) {
                t = tt;
                e0 = off_s[tt] + (s - tbase[tt]) * TE;
            }
        }
        g_tiles[2 * s] = t;
        g_tiles[2 * s + 1] = e0;
    }
}

__global__ void k_scatter(const int* __restrict__ et) {
    __shared__ int lc[NRL], lbase[NRL], lfill[NRL];
    if (threadIdx.x < NRL) { lc[threadIdx.x] = 0; lfill[threadIdx.x] = 0; }
    __syncthreads();
    int e = blockIdx.x * blockDim.x + threadIdx.x;
    int t = -1;
    if (e < EE) {
        t = et[e];
        if (t >= 0 && t < NRL) atomicAdd(&lc[t], 1); else t = -1;
    }
    __syncthreads();
    if (threadIdx.x < NRL && lc[threadIdx.x])
        lbase[threadIdx.x] = atomicAdd(&g_fill[threadIdx.x], lc[threadIdx.x]);
    __syncthreads();
    if (t >= 0) {
        int p = atomicAdd(&lfill[t], 1);
        g_eids[g_off[t] + lbase[t] + p] = e;
    }
}

// ---------------------------------------------------------------------------
// Edge GEMM via tf32 mma: msg[64,128] = Xgather(tf32) @ M_t, direct red.v2
// scatter from fragments (no output staging). smem 97KB -> 2 CTAs/SM.
constexpr int EMS_F = DD * DD;   // 16384 floats (M^T tile)
constexpr int EXS_F = TE * DD;   // 8192  (X tile)
constexpr int EDGE_SMEM = (EMS_F + EXS_F) * 4 + 2 * TE * 4;

__global__ void __launch_bounds__(256, 2) k_edge_mma(const float* __restrict__ x,
                                                     const int* __restrict__ ei) {
    extern __shared__ float sm[];
    float* Ms = sm;
    float* Xs = sm + EMS_F;
    int* srcs = (int*)(Xs + EXS_F);
    int* dsts = srcs + TE;

    int t = g_tiles[2 * blockIdx.x];
    if (t < 0) return;
    int e0 = g_tiles[2 * blockIdx.x + 1];
    int cnt = g_off[t + 1] - e0;
    if (cnt > TE) cnt = TE;
    int tid = threadIdx.x;

    if (tid < TE) {
        int s = -1, d = -1;
        if (tid < cnt) {
            int e = g_eids[e0 + tid];
            s = ei[e];
            d = ei[EE + e];
            if (s < 0 || s >= NND) s = -1;
            if (d < 0 || d >= NND) d = -1;
        }
        srcs[tid] = s;
        dsts[tid] = d;
    }
    __syncthreads();

    // load M^T tile (already tf32) with xor swizzle of 16B units within a 128-float row
    const float4* Msrc = (const float4*)(g_Mt + t * EMS_F);
#pragma unroll
    for (int j = 0; j < 16; j++) {
        int l = tid + j * 256;          // 4096 float4
        int r = l >> 5, u = l & 31;
        float4 v = Msrc[l];
        *(float4*)&Ms[r * DD + ((u ^ (r & 7)) << 2)] = v;
    }
    // gather X rows, round to tf32, same swizzle
#pragma unroll
    for (int j = 0; j < 8; j++) {
        int l = tid + j * 256;          // 2048 float4
        int r = l >> 5, u = l & 31;
        int s = srcs[r];
        float4 v = make_float4(0.f, 0.f, 0.f, 0.f);
        if (s >= 0) v = ((const float4*)(x + (size_t)s * DD))[u];
        v.x = f2tff(v.x); v.y = f2tff(v.y); v.z = f2tff(v.z); v.w = f2tff(v.w);
        *(float4*)&Xs[r * DD + ((u ^ (r & 7)) << 2)] = v;
    }
    __syncthreads();

    int lane = tid & 31, w = tid >> 5;
    int wm = w & 1, wn = w >> 1;                 // 2 m-bands(32 edges) x 4 n-bands(32 cols)
    uint32_t xs_base = (uint32_t)__cvta_generic_to_shared(Xs);
    uint32_t ms_base = (uint32_t)__cvta_generic_to_shared(Ms);
    int arow0 = wm * 32 + (lane & 15);
    int brow0 = wn * 32 + (lane & 15);

    float d[2][4][4];
#pragma unroll
    for (int mi = 0; mi < 2; mi++)
#pragma unroll
        for (int ni = 0; ni < 4; ni++)
#pragma unroll
            for (int c = 0; c < 4; c++) d[mi][ni][c] = 0.f;

#pragma unroll
    for (int ks = 0; ks < 16; ks++) {
        int uu = ks * 2 + (lane >> 4);
        uint32_t a[2][4], b[2][4];
#pragma unroll
        for (int mi = 0; mi < 2; mi++) {
            int r = arow0 + mi * 16;
            ldsm4(a[mi], xs_base + (uint32_t)((r * DD + ((uu ^ (r & 7)) << 2)) * 4));
        }
#pragma unroll
        for (int pp = 0; pp < 2; pp++) {
            int r = brow0 + pp * 16;
            ldsm4(b[pp], ms_base + (uint32_t)((r * DD + ((uu ^ (r & 7)) << 2)) * 4));
        }
#pragma unroll
        for (int mi = 0; mi < 2; mi++)
#pragma unroll
            for (int ni = 0; ni < 4; ni++) {
                int pp = ni >> 1, o = ni & 1;
                mma8(d[mi][ni], a[mi], b[pp][o], b[pp][2 + o]);
            }
    }

    // direct scatter: each fragment owns cols (oc, oc+1) of rows er and er+8
    int ocb = wn * 32 + (lane & 3) * 2;
#pragma unroll
    for (int mi = 0; mi < 2; mi++) {
        int er = wm * 32 + mi * 16 + (lane >> 2);
        int d0 = dsts[er];
        int d1 = dsts[er + 8];
#pragma unroll
        for (int ni = 0; ni < 4; ni++) {
            int oc = ocb + ni * 8;
            if (d0 >= 0) {
                float* p = g_out + (size_t)d0 * DD + oc;
                asm volatile("red.global.add.v2.f32 [%0], {%1,%2};"
                             :: "l"(p), "f"(d[mi][ni][0]), "f"(d[mi][ni][1]) : "memory");
            }
            if (d1 >= 0) {
                float* p = g_out + (size_t)d1 * DD + oc;
                asm volatile("red.global.add.v2.f32 [%0], {%1,%2};"
                             :: "l"(p), "f"(d[mi][ni][2]), "f"(d[mi][ni][3]) : "memory");
            }
        }
    }
}

// ---------------------------------------------------------------------------
// MLP GEMM via tf32 mma: Out[r,o] = act(sum_k In[r,k]*Wt[o,k] + bias[o]).
// BM=128 BN=128 BK=32, 3-stage cp.async (96KB smem -> 2 CTAs/SM), 256 threads.
constexpr int BM = 128, BN = 128, BK = 32, NSTG = 3;
constexpr int MLP_SMEM = NSTG * (BM * BK + BN * BK) * 4;   // 98304

template <bool RELU, bool ROUND, bool CVTA>
__global__ void __launch_bounds__(256, 2) mlp_mma(const float* __restrict__ In,
                                                  const float* __restrict__ Wt,
                                                  const float* __restrict__ bias,
                                                  float* __restrict__ Out,
                                                  int Nrows, int K, int O) {
    extern __shared__ float sm[];
    float* Abuf = sm;                     // [NSTG][BM*BK]
    float* Bbuf = sm + NSTG * BM * BK;    // [NSTG][BN*BK]
    int tid = threadIdx.x, lane = tid & 31, w = tid >> 5;
    int row0 = blockIdx.x * BM, col0 = blockIdx.y * BN;
    int kt = K / BK;

    auto issue = [&](int s) {
        int buf = s % NSTG;
        uint32_t abase = (uint32_t)__cvta_generic_to_shared(Abuf + buf * BM * BK);
        uint32_t bbase = (uint32_t)__cvta_generic_to_shared(Bbuf + buf * BN * BK);
        int k0 = s * BK;
#pragma unroll
        for (int i = 0; i < 4; i++) {
            int l = tid + i * 256;
            int r = l >> 3, u = l & 7;
            int gr = row0 + r;
            bool pa = gr < Nrows;
            const float* srcA = pa ? (In + (size_t)gr * K + k0 + u * 4) : In;
            uint32_t da = abase + (uint32_t)((r * BK + ((u ^ (r & 7)) << 2)) * 4);
            asm volatile("cp.async.ca.shared.global [%0], [%1], 16, %2;"
                         :: "r"(da), "l"(srcA), "r"(pa ? 16 : 0));
            const float* srcB = Wt + (size_t)(col0 + r) * K + k0 + u * 4;
            uint32_t db = bbase + (uint32_t)((r * BK + ((u ^ (r & 7)) << 2)) * 4);
            asm volatile("cp.async.ca.shared.global [%0], [%1], 16, %2;"
                         :: "r"(db), "l"(srcB), "r"(16));
        }
    };

    int wm = w & 1, wn = w >> 1;          // 2 m-warps x 4 n-warps -> warp tile 64x32
    int arow0 = wm * 64 + (lane & 15);
    int brow0 = wn * 32 + (lane & 15);

    float d[4][4][4];
#pragma unroll
    for (int mi = 0; mi < 4; mi++)
#pragma unroll
        for (int ni = 0; ni < 4; ni++)
#pragma unroll
            for (int c = 0; c < 4; c++) d[mi][ni][c] = 0.f;

    // prologue: 2 committed groups (possibly empty) keep counts in lockstep
    issue(0);               asm volatile("cp.async.commit_group;");
    if (kt > 1) issue(1);   asm volatile("cp.async.commit_group;");

    for (int s = 0; s < kt; s++) {
        asm volatile("cp.async.wait_group %0;" :: "n"(1));
        __syncthreads();
        int buf = s % NSTG;
        uint32_t abase = (uint32_t)__cvta_generic_to_shared(Abuf + buf * BM * BK);
        uint32_t bbase = (uint32_t)__cvta_generic_to_shared(Bbuf + buf * BN * BK);

#pragma unroll
        for (int ks = 0; ks < 4; ks++) {
            int uu = ks * 2 + (lane >> 4);
            uint32_t a[4][4], b[2][4];
#pragma unroll
            for (int mi = 0; mi < 4; mi++) {
                int r = arow0 + mi * 16;
                ldsm4(a[mi], abase + (uint32_t)((r * BK + ((uu ^ (r & 7)) << 2)) * 4));
            }
            if (CVTA) {
#pragma unroll
                for (int mi = 0; mi < 4; mi++)
#pragma unroll
                    for (int j = 0; j < 4; j++)
                        a[mi][j] = f2tf(__uint_as_float(a[mi][j]));
            }
#pragma unroll
            for (int pp = 0; pp < 2; pp++) {
                int r = brow0 + pp * 16;
                ldsm4(b[pp], bbase + (uint32_t)((r * BK + ((uu ^ (r & 7)) << 2)) * 4));
            }
#pragma unroll
            for (int mi = 0; mi < 4; mi++)
#pragma unroll
                for (int ni = 0; ni < 4; ni++) {
                    int pp = ni >> 1, o = ni & 1;
                    mma8(d[mi][ni], a[mi], b[pp][o], b[pp][2 + o]);
                }
        }
        if (s + 2 < kt) issue(s + 2);
        asm volatile("cp.async.commit_group;");
    }

    // epilogue: bias (+relu) (+tf32 round), guarded float2 stores
#pragma unroll
    for (int ni = 0; ni < 4; ni++) {
        int gc = col0 + wn * 32 + ni * 8 + (lane & 3) * 2;
        float bj0 = bias[gc], bj1 = bias[gc + 1];
#pragma unroll
        for (int mi = 0; mi < 4; mi++) {
            int gr = row0 + wm * 64 + mi * 16 + (lane >> 2);
            float v0 = d[mi][ni][0] + bj0, v1 = d[mi][ni][1] + bj1;
            float v2 = d[mi][ni][2] + bj0, v3 = d[mi][ni][3] + bj1;
            if (RELU) {
                v0 = fmaxf(v0, 0.f); v1 = fmaxf(v1, 0.f);
                v2 = fmaxf(v2, 0.f); v3 = fmaxf(v3, 0.f);
            }
            if (ROUND) {
                v0 = f2tff(v0); v1 = f2tff(v1); v2 = f2tff(v2); v3 = f2tff(v3);
            }
            if (gr < Nrows)     *(float2*)&Out[(size_t)gr * O + gc]       = make_float2(v0, v1);
            if (gr + 8 < Nrows) *(float2*)&Out[(size_t)(gr + 8) * O + gc] = make_float2(v2, v3);
        }
    }
}

// ---------------------------------------------------------------------------
extern "C" void kernel_launch(void* const* d_in, const int* in_sizes, int n_in,
                              void* d_out, int out_size) {
    const float* x     = (const float*)d_in[0];
    const int*   ei    = (const int*)d_in[1];
    const int*   et    = (const int*)d_in[2];
    const float* W     = (const float*)d_in[3];
    const float* eps   = (const float*)d_in[4];
    const float* A_emb = (const float*)d_in[5];
    const float* B_emb = (const float*)d_in[6];
    const float* W1    = (const float*)d_in[7];
    const float* b1    = (const float*)d_in[8];
    const float* W2    = (const float*)d_in[9];
    const float* b2    = (const float*)d_in[10];
    const float* W3    = (const float*)d_in[11];
    const float* b3    = (const float*)d_in[12];
    float* out = (float*)d_out;

    void *p_out_v, *p_h1_v, *p_h2_v, *p_w1_v, *p_w2_v, *p_w3_v;
    cudaGetSymbolAddress(&p_out_v, g_out);
    cudaGetSymbolAddress(&p_h1_v, g_h1);
    cudaGetSymbolAddress(&p_h2_v, g_h2);
    cudaGetSymbolAddress(&p_w1_v, g_W1r);
    cudaGetSymbolAddress(&p_w2_v, g_W2r);
    cudaGetSymbolAddress(&p_w3_v, g_W3r);
    float* p_out = (float*)p_out_v;
    float* p_h1  = (float*)p_h1_v;
    float* p_h2  = (float*)p_h2_v;

    cudaFuncSetAttribute(k_edge_mma, cudaFuncAttributeMaxDynamicSharedMemorySize, EDGE_SMEM);
    cudaFuncSetAttribute(mlp_mma<true, true, true>,   cudaFuncAttributeMaxDynamicSharedMemorySize, MLP_SMEM);
    cudaFuncSetAttribute(mlp_mma<true, true, false>,  cudaFuncAttributeMaxDynamicSharedMemorySize, MLP_SMEM);
    cudaFuncSetAttribute(mlp_mma<false, false, false>,cudaFuncAttributeMaxDynamicSharedMemorySize, MLP_SMEM);

    k_clear<<<1, 32>>>();
    k_build_M<<<NRL, 256>>>(W, A_emb, B_emb);
    k_round_w<<<(H * H + 255) / 256, 256>>>(W1, W2, W3);
    k_init_out<<<(NND * DD / 4 + 255) / 256, 256>>>(x, eps);
    k_hist<<<(EE + 255) / 256, 256>>>(et);
    k_build_tiles<<<1, 256>>>();
    k_scatter<<<(EE + 255) / 256, 256>>>(et);
    k_edge_mma<<<MAXTILES, 256, EDGE_SMEM>>>(x, ei);

    int gx = (NND + BM - 1) / BM;   // 782
    dim3 g12(gx, H / BN);           // (782, 2)
    mlp_mma<true, true, true><<<g12, 256, MLP_SMEM>>>(p_out, (const float*)p_w1_v, b1, p_h1, NND, DD, H);
    mlp_mma<true, true, false><<<g12, 256, MLP_SMEM>>>(p_h1, (const float*)p_w2_v, b2, p_h2, NND, H, H);
    dim3 g3(gx, DD / BN);           // (782, 1)
    mlp_mma<false, false, false><<<g3, 256, MLP_SMEM>>>(p_h2, (const float*)p_w3_v, b3, out, NND, H, DD);
}

// round 5
// speedup vs baseline: 4.2897x; 1.4973x over previous
#include <cuda_runtime.h>
#include <cuda_fp16.h>
#include <cstdint>

constexpr int NND = 100000;
constexpr int DD  = 128;
constexpr int EE  = 250000;
constexpr int NRL = 16;
constexpr int RR  = 8;
constexpr int H   = 256;
constexpr int TE  = 64;
constexpr int MAXTILES = 4096;

// Static device scratch
__device__ __half g_Mh[NRL * DD * DD];          // fused M^T per relation, fp16, [t][o][i]
__device__ float  g_out[(size_t)NND * DD];      // GIN pre-MLP accumulator (fp32)
__device__ __half g_xh[(size_t)NND * DD];       // fp16 copy of g_out for MLP layer1
__device__ __half g_h1[(size_t)NND * H];
__device__ __half g_h2[(size_t)NND * H];
__device__ __half g_W1h[H * DD];
__device__ __half g_W2h[H * H];
__device__ __half g_W3h[DD * H];
__device__ int    g_eids[EE];
__device__ int    g_cnt[NRL];
__device__ int    g_off[NRL + 1];
__device__ int    g_fill[NRL];
__device__ int    g_tiles[MAXTILES * 2];

// ---------------------------------------------------------------------------
__device__ __forceinline__ void ldsm4(uint32_t* r, uint32_t addr) {
    asm volatile("ldmatrix.sync.aligned.m8n8.x4.shared.b16 {%0,%1,%2,%3}, [%4];"
                 : "=r"(r[0]), "=r"(r[1]), "=r"(r[2]), "=r"(r[3]) : "r"(addr));
}
__device__ __forceinline__ void mma16(float* d, const uint32_t* a, uint32_t b0, uint32_t b1) {
    asm volatile(
        "mma.sync.aligned.m16n8k16.row.col.f32.f16.f16.f32 "
        "{%0,%1,%2,%3},{%4,%5,%6,%7},{%8,%9},{%0,%1,%2,%3};"
        : "+f"(d[0]), "+f"(d[1]), "+f"(d[2]), "+f"(d[3])
        : "r"(a[0]), "r"(a[1]), "r"(a[2]), "r"(a[3]), "r"(b0), "r"(b1));
}
// pack 8 floats -> 8 halves (4 uint32)
__device__ __forceinline__ void pack8h(uint32_t* o, const float* f) {
#pragma unroll
    for (int i = 0; i < 4; i++) {
        __half2 h = __floats2half2_rn(f[2 * i], f[2 * i + 1]);
        o[i] = *(uint32_t*)&h;
    }
}

// ---------------------------------------------------------------------------
__global__ void k_clear() {
    int i = threadIdx.x;
    if (i < NRL) { g_cnt[i] = 0; g_fill[i] = 0; }
}

// g_Mh[t][o][i] = half( W[o,i] + sum_k B_t[i,k] * A_t[o,k] )
__global__ void k_build_M(const float* __restrict__ W,
                          const float* __restrict__ A_emb,
                          const float* __restrict__ B_emb) {
    int t = blockIdx.x;
    __shared__ float As[DD * RR];
    __shared__ float Bs[DD * RR];
    for (int i = threadIdx.x; i < DD * RR; i += blockDim.x) {
        As[i] = A_emb[(size_t)t * DD * RR + i];
        Bs[i] = B_emb[(size_t)t * DD * RR + i];
    }
    __syncthreads();
    for (int idx = threadIdx.x; idx < DD * DD; idx += blockDim.x) {
        int o = idx >> 7;
        int i = idx & 127;
        float s = W[o * DD + i];
#pragma unroll
        for (int k = 0; k < RR; k++) s += Bs[i * RR + k] * As[o * RR + k];
        g_Mh[t * DD * DD + o * DD + i] = __float2half_rn(s);
    }
}

// convert MLP weights to fp16 once
__global__ void k_cvt_w(const float* __restrict__ W1, const float* __restrict__ W2,
                        const float* __restrict__ W3) {
    int i = blockIdx.x * blockDim.x + threadIdx.x;
    if (i < H * DD) g_W1h[i] = __float2half_rn(W1[i]);
    if (i < H * H)  g_W2h[i] = __float2half_rn(W2[i]);
    if (i < DD * H) g_W3h[i] = __float2half_rn(W3[i]);
}

__global__ void k_init_out(const float* __restrict__ x, const float* __restrict__ eps) {
    float s = 1.0f + eps[0];
    int i = blockIdx.x * blockDim.x + threadIdx.x;
    int total = NND * DD / 4;
    if (i < total) {
        float4 v = ((const float4*)x)[i];
        v.x *= s; v.y *= s; v.z *= s; v.w *= s;
        ((float4*)g_out)[i] = v;
    }
}

// g_xh = fp16(g_out), after edge aggregation
__global__ void k_cvt_x() {
    int i = blockIdx.x * blockDim.x + threadIdx.x;
    int total = NND * DD / 4;
    if (i < total) {
        float4 v = ((const float4*)g_out)[i];
        __half2 h0 = __floats2half2_rn(v.x, v.y);
        __half2 h1 = __floats2half2_rn(v.z, v.w);
        uint2 u; u.x = *(uint32_t*)&h0; u.y = *(uint32_t*)&h1;
        ((uint2*)g_xh)[i] = u;
    }
}

__global__ void k_hist(const int* __restrict__ et) {
    __shared__ int lc[NRL];
    if (threadIdx.x < NRL) lc[threadIdx.x] = 0;
    __syncthreads();
    int e = blockIdx.x * blockDim.x + threadIdx.x;
    if (e < EE) {
        int t = et[e];
        if (t >= 0 && t < NRL) atomicAdd(&lc[t], 1);
    }
    __syncthreads();
    if (threadIdx.x < NRL && lc[threadIdx.x]) atomicAdd(&g_cnt[threadIdx.x], lc[threadIdx.x]);
}

__global__ void k_build_tiles() {
    __shared__ int off_s[NRL + 1], tbase[NRL + 1];
    if (threadIdx.x == 0) {
        int acc = 0;
        for (int t = 0; t < NRL; t++) { off_s[t] = acc; acc += g_cnt[t]; }
        off_s[NRL] = acc;
        int tb = 0;
        for (int t = 0; t < NRL; t++) { tbase[t] = tb; tb += (g_cnt[t] + TE - 1) / TE; }
        tbase[NRL] = tb;
        for (int t = 0; t <= NRL; t++) g_off[t] = off_s[t];
    }
    __syncthreads();
    for (int s = threadIdx.x; s < MAXTILES; s += blockDim.x) {
        int t = -1, e0 = 0;
        for (int tt = 0; tt < NRL; tt++) {
            if (s >= tbase[tt] && s < tbase[tt + 1]) {
                t = tt;
                e0 = off_s[tt] + (s - tbase[tt]) * TE;
            }
        }
        g_tiles[2 * s] = t;
        g_tiles[2 * s + 1] = e0;
    }
}

__global__ void k_scatter(const int* __restrict__ et) {
    __shared__ int lc[NRL], lbase[NRL], lfill[NRL];
    if (threadIdx.x < NRL) { lc[threadIdx.x] = 0; lfill[threadIdx.x] = 0; }
    __syncthreads();
    int e = blockIdx.x * blockDim.x + threadIdx.x;
    int t = -1;
    if (e < EE) {
        t = et[e];
        if (t >= 0 && t < NRL) atomicAdd(&lc[t], 1); else t = -1;
    }
    __syncthreads();
    if (threadIdx.x < NRL && lc[threadIdx.x])
        lbase[threadIdx.x] = atomicAdd(&g_fill[threadIdx.x], lc[threadIdx.x]);
    __syncthreads();
    if (t >= 0) {
        int p = atomicAdd(&lfill[t], 1);
        g_eids[g_off[t] + lbase[t] + p] = e;
    }
}

// ---------------------------------------------------------------------------
// Edge GEMM via fp16 mma: msg[64,128] = Xgather(fp16) @ M_t(fp16), fp32 accum,
// direct red.v2 scatter. Tiles: Ms 128x128 halves (32KB), Xs 64x128 (16KB).
// Rows are 16 units of 16B; swizzle xor low-3-bits of unit with (row&7).
constexpr int EDGE_SMEM = (DD * DD + TE * DD) * 2 + 2 * TE * 4;

__global__ void __launch_bounds__(256, 3) k_edge_mma(const float* __restrict__ x,
                                                     const int* __restrict__ ei) {
    extern __shared__ char smc[];
    __half* Ms = (__half*)smc;                    // 128x128 halves
    __half* Xs = Ms + DD * DD;                    // 64x128 halves
    int* srcs = (int*)(Xs + TE * DD);
    int* dsts = srcs + TE;

    int t = g_tiles[2 * blockIdx.x];
    if (t < 0) return;
    int e0 = g_tiles[2 * blockIdx.x + 1];
    int cnt = g_off[t + 1] - e0;
    if (cnt > TE) cnt = TE;
    int tid = threadIdx.x;

    if (tid < TE) {
        int s = -1, d = -1;
        if (tid < cnt) {
            int e = g_eids[e0 + tid];
            s = ei[e];
            d = ei[EE + e];
            if (s < 0 || s >= NND) s = -1;
            if (d < 0 || d >= NND) d = -1;
        }
        srcs[tid] = s;
        dsts[tid] = d;
    }
    __syncthreads();

    // load M^T tile (fp16): 2048 16B-units
    const uint4* Msrc = (const uint4*)(g_Mh + (size_t)t * DD * DD);
#pragma unroll
    for (int j = 0; j < 8; j++) {
        int l = tid + j * 256;
        int r = l >> 4, u = l & 15;
        uint4 v = Msrc[l];
        *(uint4*)((char*)Ms + (r * 16 + (u ^ (r & 7))) * 16) = v;
    }
    // gather X rows, cvt to fp16: 1024 16B-units (8 halves each = 8 floats in)
#pragma unroll
    for (int j = 0; j < 4; j++) {
        int l = tid + j * 256;
        int r = l >> 4, u = l & 15;
        int s = srcs[r];
        float f[8];
        if (s >= 0) {
            float4 a = ((const float4*)(x + (size_t)s * DD))[u * 2];
            float4 b = ((const float4*)(x + (size_t)s * DD))[u * 2 + 1];
            f[0]=a.x; f[1]=a.y; f[2]=a.z; f[3]=a.w;
            f[4]=b.x; f[5]=b.y; f[6]=b.z; f[7]=b.w;
        } else {
#pragma unroll
            for (int q = 0; q < 8; q++) f[q] = 0.f;
        }
        uint32_t h[4];
        pack8h(h, f);
        *(uint4*)((char*)Xs + (r * 16 + (u ^ (r & 7))) * 16) = make_uint4(h[0], h[1], h[2], h[3]);
    }
    __syncthreads();

    int lane = tid & 31, w = tid >> 5;
    int wm = w & 1, wn = w >> 1;                 // 2 m-bands(32 edges) x 4 n-bands(32 cols)
    uint32_t xs_base = (uint32_t)__cvta_generic_to_shared(Xs);
    uint32_t ms_base = (uint32_t)__cvta_generic_to_shared(Ms);
    int arow0 = wm * 32 + (lane & 15);
    int brow0 = wn * 32 + (lane & 15);

    float d[2][4][4];
#pragma unroll
    for (int mi = 0; mi < 2; mi++)
#pragma unroll
        for (int ni = 0; ni < 4; ni++)
#pragma unroll
            for (int c = 0; c < 4; c++) d[mi][ni][c] = 0.f;

#pragma unroll
    for (int ks = 0; ks < 8; ks++) {             // 8 k16 steps over K=128
        int uu = ks * 2 + (lane >> 4);
        uint32_t a[2][4], b[2][4];
#pragma unroll
        for (int mi = 0; mi < 2; mi++) {
            int r = arow0 + mi * 16;
            ldsm4(a[mi], xs_base + (uint32_t)((r * 16 + (uu ^ (r & 7))) * 16));
        }
#pragma unroll
        for (int pp = 0; pp < 2; pp++) {
            int r = brow0 + pp * 16;
            ldsm4(b[pp], ms_base + (uint32_t)((r * 16 + (uu ^ (r & 7))) * 16));
        }
#pragma unroll
        for (int mi = 0; mi < 2; mi++)
#pragma unroll
            for (int ni = 0; ni < 4; ni++) {
                int pp = ni >> 1, o = ni & 1;
                mma16(d[mi][ni], a[mi], b[pp][o], b[pp][2 + o]);
            }
    }

    // direct scatter: each fragment owns cols (oc, oc+1) of rows er and er+8
    int ocb = wn * 32 + (lane & 3) * 2;
#pragma unroll
    for (int mi = 0; mi < 2; mi++) {
        int er = wm * 32 + mi * 16 + (lane >> 2);
        int d0 = dsts[er];
        int d1 = dsts[er + 8];
#pragma unroll
        for (int ni = 0; ni < 4; ni++) {
            int oc = ocb + ni * 8;
            if (d0 >= 0) {
                float* p = g_out + (size_t)d0 * DD + oc;
                asm volatile("red.global.add.v2.f32 [%0], {%1,%2};"
                             :: "l"(p), "f"(d[mi][ni][0]), "f"(d[mi][ni][1]) : "memory");
            }
            if (d1 >= 0) {
                float* p = g_out + (size_t)d1 * DD + oc;
                asm volatile("red.global.add.v2.f32 [%0], {%1,%2};"
                             :: "l"(p), "f"(d[mi][ni][2]), "f"(d[mi][ni][3]) : "memory");
            }
        }
    }
}

// ---------------------------------------------------------------------------
// MLP GEMM via fp16 mma: Out[r,o] = act(sum_k In[r,k]*Wt[o,k] + bias[o]).
// In/Wt fp16, accum fp32. BM=128 BN=128 BK=64(halves), 3-stage cp.async,
// 32KB/stage -> 96KB smem -> 2 CTAs/SM. 256 threads, warp tile 64x32.
constexpr int BM = 128, BN = 128, BKH = 64, NSTG = 3;
constexpr int STAGE_A = BM * BKH;              // halves
constexpr int STAGE_B = BN * BKH;
constexpr int MLP_SMEM = NSTG * (STAGE_A + STAGE_B) * 2;   // 98304 bytes

template <bool RELU, bool OUT_HALF>
__global__ void __launch_bounds__(256, 2) mlp_mma(const __half* __restrict__ In,
                                                  const __half* __restrict__ Wt,
                                                  const float* __restrict__ bias,
                                                  void* __restrict__ OutV,
                                                  int Nrows, int K, int O) {
    extern __shared__ char smc[];
    __half* Abuf = (__half*)smc;
    __half* Bbuf = Abuf + NSTG * STAGE_A;
    int tid = threadIdx.x, lane = tid & 31, w = tid >> 5;
    int row0 = blockIdx.x * BM, col0 = blockIdx.y * BN;
    int kt = K / BKH;

    auto issue = [&](int s) {
        int buf = s % NSTG;
        uint32_t abase = (uint32_t)__cvta_generic_to_shared(Abuf + buf * STAGE_A);
        uint32_t bbase = (uint32_t)__cvta_generic_to_shared(Bbuf + buf * STAGE_B);
        int k0 = s * BKH;
#pragma unroll
        for (int i = 0; i < 4; i++) {
            int l = tid + i * 256;
            int r = l >> 3, u = l & 7;               // 128 rows x 8 units
            int gr = row0 + r;
            bool pa = gr < Nrows;
            const __half* srcA = pa ? (In + (size_t)gr * K + k0 + u * 8) : In;
            uint32_t da = abase * 0 + abase + (uint32_t)((r * 8 + (u ^ (r & 7))) * 16);
            asm volatile("cp.async.ca.shared.global [%0], [%1], 16, %2;"
                         :: "r"(da), "l"(srcA), "r"(pa ? 16 : 0));
            const __half* srcB = Wt + (size_t)(col0 + r) * K + k0 + u * 8;
            uint32_t db = bbase + (uint32_t)((r * 8 + (u ^ (r & 7))) * 16);
            asm volatile("cp.async.ca.shared.global [%0], [%1], 16, %2;"
                         :: "r"(db), "l"(srcB), "r"(16));
        }
    };

    int wm = w & 1, wn = w >> 1;          // 2 m-warps x 4 n-warps -> warp tile 64x32
    int arow0 = wm * 64 + (lane & 15);
    int brow0 = wn * 32 + (lane & 15);

    float d[4][4][4];
#pragma unroll
    for (int mi = 0; mi < 4; mi++)
#pragma unroll
        for (int ni = 0; ni < 4; ni++)
#pragma unroll
            for (int c = 0; c < 4; c++) d[mi][ni][c] = 0.f;

    issue(0);               asm volatile("cp.async.commit_group;");
    if (kt > 1) issue(1);   asm volatile("cp.async.commit_group;");

    for (int s = 0; s < kt; s++) {
        asm volatile("cp.async.wait_group %0;" :: "n"(1));
        __syncthreads();
        int buf = s % NSTG;
        uint32_t abase = (uint32_t)__cvta_generic_to_shared(Abuf + buf * STAGE_A);
        uint32_t bbase = (uint32_t)__cvta_generic_to_shared(Bbuf + buf * STAGE_B);

#pragma unroll
        for (int ks = 0; ks < 4; ks++) {            // 4 k16 steps per BK=64
            int uu = ks * 2 + (lane >> 4);
            uint32_t a[4][4], b[2][4];
#pragma unroll
            for (int mi = 0; mi < 4; mi++) {
                int r = arow0 + mi * 16;
                ldsm4(a[mi], abase + (uint32_t)((r * 8 + (uu ^ (r & 7))) * 16));
            }
#pragma unroll
            for (int pp = 0; pp < 2; pp++) {
                int r = brow0 + pp * 16;
                ldsm4(b[pp], bbase + (uint32_t)((r * 8 + (uu ^ (r & 7))) * 16));
            }
#pragma unroll
            for (int mi = 0; mi < 4; mi++)
#pragma unroll
                for (int ni = 0; ni < 4; ni++) {
                    int pp = ni >> 1, o = ni & 1;
                    mma16(d[mi][ni], a[mi], b[pp][o], b[pp][2 + o]);
                }
        }
        if (s + 2 < kt) issue(s + 2);
        asm volatile("cp.async.commit_group;");
    }

    // epilogue
#pragma unroll
    for (int ni = 0; ni < 4; ni++) {
        int gc = col0 + wn * 32 + ni * 8 + (lane & 3) * 2;
        float bj0 = bias[gc], bj1 = bias[gc + 1];
#pragma unroll
        for (int mi = 0; mi < 4; mi++) {
            int gr = row0 + wm * 64 + mi * 16 + (lane >> 2);
            float v0 = d[mi][ni][0] + bj0, v1 = d[mi][ni][1] + bj1;
            float v2 = d[mi][ni][2] + bj0, v3 = d[mi][ni][3] + bj1;
            if (RELU) {
                v0 = fmaxf(v0, 0.f); v1 = fmaxf(v1, 0.f);
                v2 = fmaxf(v2, 0.f); v3 = fmaxf(v3, 0.f);
            }
            if (OUT_HALF) {
                __half* Out = (__half*)OutV;
                __half2 h0 = __floats2half2_rn(v0, v1);
                __half2 h1 = __floats2half2_rn(v2, v3);
                if (gr < Nrows)     *(__half2*)&Out[(size_t)gr * O + gc]       = h0;
                if (gr + 8 < Nrows) *(__half2*)&Out[(size_t)(gr + 8) * O + gc] = h1;
            } else {
                float* Out = (float*)OutV;
                if (gr < Nrows)     *(float2*)&Out[(size_t)gr * O + gc]       = make_float2(v0, v1);
                if (gr + 8 < Nrows) *(float2*)&Out[(size_t)(gr + 8) * O + gc] = make_float2(v2, v3);
            }
        }
    }
}

// ---------------------------------------------------------------------------
extern "C" void kernel_launch(void* const* d_in, const int* in_sizes, int n_in,
                              void* d_out, int out_size) {
    const float* x     = (const float*)d_in[0];
    const int*   ei    = (const int*)d_in[1];
    const int*   et    = (const int*)d_in[2];
    const float* W     = (const float*)d_in[3];
    const float* eps   = (const float*)d_in[4];
    const float* A_emb = (const float*)d_in[5];
    const float* B_emb = (const float*)d_in[6];
    const float* W1    = (const float*)d_in[7];
    const float* b1    = (const float*)d_in[8];
    const float* W2    = (const float*)d_in[9];
    const float* b2    = (const float*)d_in[10];
    const float* W3    = (const float*)d_in[11];
    const float* b3    = (const float*)d_in[12];
    float* out = (float*)d_out;

    void *p_xh, *p_h1, *p_h2, *p_w1, *p_w2, *p_w3;
    cudaGetSymbolAddress(&p_xh, g_xh);
    cudaGetSymbolAddress(&p_h1, g_h1);
    cudaGetSymbolAddress(&p_h2, g_h2);
    cudaGetSymbolAddress(&p_w1, g_W1h);
    cudaGetSymbolAddress(&p_w2, g_W2h);
    cudaGetSymbolAddress(&p_w3, g_W3h);

    cudaFuncSetAttribute(k_edge_mma, cudaFuncAttributeMaxDynamicSharedMemorySize, EDGE_SMEM);
    cudaFuncSetAttribute(mlp_mma<true, true>,   cudaFuncAttributeMaxDynamicSharedMemorySize, MLP_SMEM);
    cudaFuncSetAttribute(mlp_mma<false, false>, cudaFuncAttributeMaxDynamicSharedMemorySize, MLP_SMEM);

    k_clear<<<1, 32>>>();
    k_build_M<<<NRL, 256>>>(W, A_emb, B_emb);
    k_cvt_w<<<(H * H + 255) / 256, 256>>>(W1, W2, W3);
    k_init_out<<<(NND * DD / 4 + 255) / 256, 256>>>(x, eps);
    k_hist<<<(EE + 255) / 256, 256>>>(et);
    k_build_tiles<<<1, 256>>>();
    k_scatter<<<(EE + 255) / 256, 256>>>(et);
    k_edge_mma<<<MAXTILES, 256, EDGE_SMEM>>>(x, ei);
    k_cvt_x<<<(NND * DD / 4 + 255) / 256, 256>>>();

    int gx = (NND + BM - 1) / BM;   // 782
    dim3 g12(gx, H / BN);           // (782, 2)
    mlp_mma<true, true><<<g12, 256, MLP_SMEM>>>((const __half*)p_xh, (const __half*)p_w1, b1, p_h1, NND, DD, H);
    mlp_mma<true, true><<<g12, 256, MLP_SMEM>>>((const __half*)p_h1, (const __half*)p_w2, b2, p_h2, NND, H, H);
    dim3 g3(gx, DD / BN);           // (782, 1)
    mlp_mma<false, false><<<g3, 256, MLP_SMEM>>>((const __half*)p_h2, (const __half*)p_w3, b3, out, NND, H, DD);
}

// round 7
// speedup vs baseline: 4.5107x; 1.0515x over previous
#include <cuda_runtime.h>
#include <cuda_fp16.h>
#include <cstdint>

constexpr int NND = 100000;
constexpr int DD  = 128;
constexpr int EE  = 250000;
constexpr int NRL = 16;
constexpr int RR  = 8;
constexpr int H   = 256;
constexpr int TE  = 64;
constexpr int MAXTILES = 4096;

// Static device scratch
__device__ __half g_Mh[NRL * DD * DD];          // fused M^T per relation, fp16, [t][o][i]
__device__ float  g_out[(size_t)NND * DD];      // GIN pre-MLP accumulator (fp32)
__device__ __half g_h1[(size_t)NND * H];
__device__ __half g_h2[(size_t)NND * H];
__device__ __half g_W1h[H * DD];
__device__ __half g_W2h[H * H];
__device__ __half g_W3h[DD * H];
__device__ int    g_eids[EE];
__device__ int    g_cnt[NRL];
__device__ int    g_off[NRL + 1];
__device__ int    g_fill[NRL];
__device__ int    g_tiles[MAXTILES * 2];

// ---------------------------------------------------------------------------
__device__ __forceinline__ uint32_t smem_u32(const void* p) {
    return (uint32_t)__cvta_generic_to_shared(p);
}
__device__ __forceinline__ void ldsm4(uint32_t* r, uint32_t addr) {
    asm volatile("ldmatrix.sync.aligned.m8n8.x4.shared.b16 {%0,%1,%2,%3}, [%4];"
                 : "=r"(r[0]), "=r"(r[1]), "=r"(r[2]), "=r"(r[3]) : "r"(addr));
}
__device__ __forceinline__ void mma16(float* d, const uint32_t* a, uint32_t b0, uint32_t b1) {
    asm volatile(
        "mma.sync.aligned.m16n8k16.row.col.f32.f16.f16.f32 "
        "{%0,%1,%2,%3},{%4,%5,%6,%7},{%8,%9},{%0,%1,%2,%3};"
        : "+f"(d[0]), "+f"(d[1]), "+f"(d[2]), "+f"(d[3])
        : "r"(a[0]), "r"(a[1]), "r"(a[2]), "r"(a[3]), "r"(b0), "r"(b1));
}
__device__ __forceinline__ void pack8h(uint32_t* o, const float* f) {
#pragma unroll
    for (int i = 0; i < 4; i++) {
        __half2 h = __floats2half2_rn(f[2 * i], f[2 * i + 1]);
        o[i] = *(uint32_t*)&h;
    }
}

// ---------------------------------------------------------------------------
// Fused prep: blocks [0,16) build_M, [16,12516) init_out, [12516,13493) hist,
// [13493,13749) cvt_w. All independent.
constexpr int PREP_BM0   = 0;
constexpr int PREP_INIT0 = NRL;                       // 16
constexpr int PREP_HIST0 = PREP_INIT0 + 12500;        // 12516
constexpr int PREP_CVTW0 = PREP_HIST0 + 977;          // 13493
constexpr int PREP_GRID  = PREP_CVTW0 + 256;          // 13749

__global__ void __launch_bounds__(256) k_prep(const float* __restrict__ x,
                                              const float* __restrict__ eps,
                                              const float* __restrict__ W,
                                              const float* __restrict__ A_emb,
                                              const float* __restrict__ B_emb,
                                              const float* __restrict__ W1,
                                              const float* __restrict__ W2,
                                              const float* __restrict__ W3,
                                              const int* __restrict__ et) {
    int b = blockIdx.x;
    if (b < PREP_INIT0) {
        // build fused relation matrix, fp16
        int t = b;
        __shared__ float As[DD * RR];
        __shared__ float Bs[DD * RR];
        for (int i = threadIdx.x; i < DD * RR; i += blockDim.x) {
            As[i] = A_emb[(size_t)t * DD * RR + i];
            Bs[i] = B_emb[(size_t)t * DD * RR + i];
        }
        __syncthreads();
        for (int idx = threadIdx.x; idx < DD * DD; idx += blockDim.x) {
            int o = idx >> 7;
            int i = idx & 127;
            float s = W[o * DD + i];
#pragma unroll
            for (int k = 0; k < RR; k++) s += Bs[i * RR + k] * As[o * RR + k];
            g_Mh[t * DD * DD + o * DD + i] = __float2half_rn(s);
        }
    } else if (b < PREP_HIST0) {
        // g_out = (1+eps)*x
        float s = 1.0f + eps[0];
        int i = (b - PREP_INIT0) * 256 + threadIdx.x;
        if (i < NND * DD / 4) {
            float4 v = ((const float4*)x)[i];
            v.x *= s; v.y *= s; v.z *= s; v.w *= s;
            ((float4*)g_out)[i] = v;
        }
    } else if (b < PREP_CVTW0) {
        // relation histogram
        __shared__ int lc[NRL];
        if (threadIdx.x < NRL) lc[threadIdx.x] = 0;
        __syncthreads();
        int e = (b - PREP_HIST0) * 256 + threadIdx.x;
        if (e < EE) {
            int t = et[e];
            if (t >= 0 && t < NRL) atomicAdd(&lc[t], 1);
        }
        __syncthreads();
        if (threadIdx.x < NRL && lc[threadIdx.x]) atomicAdd(&g_cnt[threadIdx.x], lc[threadIdx.x]);
    } else {
        // weight cvt to fp16
        int i = (b - PREP_CVTW0) * 256 + threadIdx.x;
        if (i < H * DD) g_W1h[i] = __float2half_rn(W1[i]);
        if (i < H * H)  g_W2h[i] = __float2half_rn(W2[i]);
        if (i < DD * H) g_W3h[i] = __float2half_rn(W3[i]);
    }
}

__global__ void k_build_tiles() {
    __shared__ int off_s[NRL + 1], tbase[NRL + 1];
    if (threadIdx.x == 0) {
        int acc = 0;
        for (int t = 0; t < NRL; t++) { off_s[t] = acc; acc += g_cnt[t]; }
        off_s[NRL] = acc;
        int tb = 0;
        for (int t = 0; t < NRL; t++) { tbase[t] = tb; tb += (g_cnt[t] + TE - 1) / TE; }
        tbase[NRL] = tb;
        for (int t = 0; t <= NRL; t++) g_off[t] = off_s[t];
    }
    __syncthreads();
    // self-zero g_cnt for the next graph replay
    if (threadIdx.x < NRL) g_cnt[threadIdx.x] = 0;
    for (int s = threadIdx.x; s < MAXTILES; s += blockDim.x) {
        int t = -1, e0 = 0;
        for (int tt = 0; tt < NRL; tt++) {
            if (s >= tbase[tt] && s < tbase[tt + 1]) {
                t = tt;
                e0 = off_s[tt] + (s - tbase[tt]) * TE;
            }
        }
        g_tiles[2 * s] = t;
        g_tiles[2 * s + 1] = e0;
    }
}

__global__ void k_scatter(const int* __restrict__ et) {
    __shared__ int lc[NRL], lbase[NRL], lfill[NRL];
    if (threadIdx.x < NRL) { lc[threadIdx.x] = 0; lfill[threadIdx.x] = 0; }
    __syncthreads();
    int e = blockIdx.x * blockDim.x + threadIdx.x;
    int t = -1;
    if (e < EE) {
        t = et[e];
        if (t >= 0 && t < NRL) atomicAdd(&lc[t], 1); else t = -1;
    }
    __syncthreads();
    if (threadIdx.x < NRL && lc[threadIdx.x])
        lbase[threadIdx.x] = atomicAdd(&g_fill[threadIdx.x], lc[threadIdx.x]);
    __syncthreads();
    if (t >= 0) {
        int p = atomicAdd(&lfill[t], 1);
        g_eids[g_off[t] + lbase[t] + p] = e;
    }
}

// ---------------------------------------------------------------------------
// Edge GEMM via fp16 mma.sync; zeros g_fill for the next replay.
constexpr int EDGE_SMEM = (DD * DD + TE * DD) * 2 + 2 * TE * 4;

__global__ void __launch_bounds__(256, 3) k_edge_mma(const float* __restrict__ x,
                                                     const int* __restrict__ ei) {
    extern __shared__ char smc[];
    __half* Ms = (__half*)smc;
    __half* Xs = Ms + DD * DD;
    int* srcs = (int*)(Xs + TE * DD);
    int* dsts = srcs + TE;

    // self-zero g_fill for next replay (scatter of this replay already done)
    if (blockIdx.x < NRL && threadIdx.x == 0) g_fill[blockIdx.x] = 0;

    int t = g_tiles[2 * blockIdx.x];
    if (t < 0) return;
    int e0 = g_tiles[2 * blockIdx.x + 1];
    int cnt = g_off[t + 1] - e0;
    if (cnt > TE) cnt = TE;
    int tid = threadIdx.x;

    if (tid < TE) {
        int s = -1, d = -1;
        if (tid < cnt) {
            int e = g_eids[e0 + tid];
            s = ei[e];
            d = ei[EE + e];
            if (s < 0 || s >= NND) s = -1;
            if (d < 0 || d >= NND) d = -1;
        }
        srcs[tid] = s;
        dsts[tid] = d;
    }
    __syncthreads();

    const uint4* Msrc = (const uint4*)(g_Mh + (size_t)t * DD * DD);
#pragma unroll
    for (int j = 0; j < 8; j++) {
        int l = tid + j * 256;
        int r = l >> 4, u = l & 15;
        uint4 v = Msrc[l];
        *(uint4*)((char*)Ms + (r * 16 + (u ^ (r & 7))) * 16) = v;
    }
#pragma unroll
    for (int j = 0; j < 4; j++) {
        int l = tid + j * 256;
        int r = l >> 4, u = l & 15;
        int s = srcs[r];
        float f[8];
        if (s >= 0) {
            float4 a = ((const float4*)(x + (size_t)s * DD))[u * 2];
            float4 b = ((const float4*)(x + (size_t)s * DD))[u * 2 + 1];
            f[0]=a.x; f[1]=a.y; f[2]=a.z; f[3]=a.w;
            f[4]=b.x; f[5]=b.y; f[6]=b.z; f[7]=b.w;
        } else {
#pragma unroll
            for (int q = 0; q < 8; q++) f[q] = 0.f;
        }
        uint32_t h[4];
        pack8h(h, f);
        *(uint4*)((char*)Xs + (r * 16 + (u ^ (r & 7))) * 16) = make_uint4(h[0], h[1], h[2], h[3]);
    }
    __syncthreads();

    int lane = tid & 31, w = tid >> 5;
    int wm = w & 1, wn = w >> 1;
    uint32_t xs_base = smem_u32(Xs);
    uint32_t ms_base = smem_u32(Ms);
    int arow0 = wm * 32 + (lane & 15);
    int brow0 = wn * 32 + (lane & 15);

    float d[2][4][4];
#pragma unroll
    for (int mi = 0; mi < 2; mi++)
#pragma unroll
        for (int ni = 0; ni < 4; ni++)
#pragma unroll
            for (int c = 0; c < 4; c++) d[mi][ni][c] = 0.f;

#pragma unroll
    for (int ks = 0; ks < 8; ks++) {
        int uu = ks * 2 + (lane >> 4);
        uint32_t a[2][4], b[2][4];
#pragma unroll
        for (int mi = 0; mi < 2; mi++) {
            int r = arow0 + mi * 16;
            ldsm4(a[mi], xs_base + (uint32_t)((r * 16 + (uu ^ (r & 7))) * 16));
        }
#pragma unroll
        for (int pp = 0; pp < 2; pp++) {
            int r = brow0 + pp * 16;
            ldsm4(b[pp], ms_base + (uint32_t)((r * 16 + (uu ^ (r & 7))) * 16));
        }
#pragma unroll
        for (int mi = 0; mi < 2; mi++)
#pragma unroll
            for (int ni = 0; ni < 4; ni++) {
                int pp = ni >> 1, o = ni & 1;
                mma16(d[mi][ni], a[mi], b[pp][o], b[pp][2 + o]);
            }
    }

    int ocb = wn * 32 + (lane & 3) * 2;
#pragma unroll
    for (int mi = 0; mi < 2; mi++) {
        int er = wm * 32 + mi * 16 + (lane >> 2);
        int d0 = dsts[er];
        int d1 = dsts[er + 8];
#pragma unroll
        for (int ni = 0; ni < 4; ni++) {
            int oc = ocb + ni * 8;
            if (d0 >= 0) {
                float* p = g_out + (size_t)d0 * DD + oc;
                asm volatile("red.global.add.v2.f32 [%0], {%1,%2};"
                             :: "l"(p), "f"(d[mi][ni][0]), "f"(d[mi][ni][1]) : "memory");
            }
            if (d1 >= 0) {
                float* p = g_out + (size_t)d1 * DD + oc;
                asm volatile("red.global.add.v2.f32 [%0], {%1,%2};"
                             :: "l"(p), "f"(d[mi][ni][2]), "f"(d[mi][ni][3]) : "memory");
            }
        }
    }
}

// ---------------------------------------------------------------------------
// MLP GEMM via fp16 mma.sync. IN_FLOAT: A source is fp32 (g_out), converted
// in-register during a synchronous load path (replaces the k_cvt_x pass).
constexpr int BM = 128, BN = 128, BKH = 64, NSTG = 3;
constexpr int STAGE_A = BM * BKH;              // halves
constexpr int STAGE_B = BN * BKH;
constexpr int MLP_SMEM = NSTG * (STAGE_A + STAGE_B) * 2;   // 98304 bytes

template <bool RELU, bool OUT_HALF, bool IN_FLOAT>
__global__ void __launch_bounds__(256, 2) mlp_mma(const void* __restrict__ InV,
                                                  const __half* __restrict__ Wt,
                                                  const float* __restrict__ bias,
                                                  void* __restrict__ OutV,
                                                  int Nrows, int K, int O) {
    extern __shared__ char smc[];
    __half* Abuf = (__half*)smc;
    __half* Bbuf = Abuf + NSTG * STAGE_A;
    int tid = threadIdx.x, lane = tid & 31, w = tid >> 5;
    int row0 = blockIdx.x * BM, col0 = blockIdx.y * BN;
    int kt = K / BKH;

    auto issue = [&](int s) {
        int buf = s % NSTG;
        uint32_t abase = smem_u32(Abuf + buf * STAGE_A);
        uint32_t bbase = smem_u32(Bbuf + buf * STAGE_B);
        int k0 = s * BKH;
#pragma unroll
        for (int i = 0; i < 4; i++) {
            int l = tid + i * 256;
            int r = l >> 3, u = l & 7;               // 128 rows x 8 16B-units
            int gr = row0 + r;
            bool pa = gr < Nrows;
            if (IN_FLOAT) {
                const float* In = (const float*)InV;
                float f[8];
                if (pa) {
                    const float4* src = (const float4*)(In + (size_t)gr * K + k0 + u * 8);
                    float4 a = src[0], b = src[1];
                    f[0]=a.x; f[1]=a.y; f[2]=a.z; f[3]=a.w;
                    f[4]=b.x; f[5]=b.y; f[6]=b.z; f[7]=b.w;
                } else {
#pragma unroll
                    for (int q = 0; q < 8; q++) f[q] = 0.f;
                }
                uint32_t h[4];
                pack8h(h, f);
                *(uint4*)(Abuf + buf * STAGE_A + (r * 8 + (u ^ (r & 7))) * 8) =
                    make_uint4(h[0], h[1], h[2], h[3]);
            } else {
                const __half* In = (const __half*)InV;
                const __half* srcA = pa ? (In + (size_t)gr * K + k0 + u * 8) : In;
                uint32_t da = abase + (uint32_t)((r * 8 + (u ^ (r & 7))) * 16);
                asm volatile("cp.async.ca.shared.global [%0], [%1], 16, %2;"
                             :: "r"(da), "l"(srcA), "r"(pa ? 16 : 0));
            }
            const __half* srcB = Wt + (size_t)(col0 + r) * K + k0 + u * 8;
            uint32_t db = bbase + (uint32_t)((r * 8 + (u ^ (r & 7))) * 16);
            asm volatile("cp.async.ca.shared.global [%0], [%1], 16, %2;"
                         :: "r"(db), "l"(srcB), "r"(16));
        }
    };

    int wm = w & 1, wn = w >> 1;          // 2 m-warps x 4 n-warps -> warp tile 64x32
    int arow0 = wm * 64 + (lane & 15);
    int brow0 = wn * 32 + (lane & 15);

    float d[4][4][4];
#pragma unroll
    for (int mi = 0; mi < 4; mi++)
#pragma unroll
        for (int ni = 0; ni < 4; ni++)
#pragma unroll
            for (int c = 0; c < 4; c++) d[mi][ni][c] = 0.f;

    issue(0);               asm volatile("cp.async.commit_group;");
    if (kt > 1) issue(1);   asm volatile("cp.async.commit_group;");

    for (int s = 0; s < kt; s++) {
        asm volatile("cp.async.wait_group %0;" :: "n"(1));
        __syncthreads();
        int buf = s % NSTG;
        uint32_t abase = smem_u32(Abuf + buf * STAGE_A);
        uint32_t bbase = smem_u32(Bbuf + buf * STAGE_B);

#pragma unroll
        for (int ks = 0; ks < 4; ks++) {            // 4 k16 steps per BK=64
            int uu = ks * 2 + (lane >> 4);
            uint32_t a[4][4], b[2][4];
#pragma unroll
            for (int mi = 0; mi < 4; mi++) {
                int r = arow0 + mi * 16;
                ldsm4(a[mi], abase + (uint32_t)((r * 8 + (uu ^ (r & 7))) * 16));
            }
#pragma unroll
            for (int pp = 0; pp < 2; pp++) {
                int r = brow0 + pp * 16;
                ldsm4(b[pp], bbase + (uint32_t)((r * 8 + (uu ^ (r & 7))) * 16));
            }
#pragma unroll
            for (int mi = 0; mi < 4; mi++)
#pragma unroll
                for (int ni = 0; ni < 4; ni++) {
                    int pp = ni >> 1, o = ni & 1;
                    mma16(d[mi][ni], a[mi], b[pp][o], b[pp][2 + o]);
                }
        }
        if (s + 2 < kt) issue(s + 2);
        asm volatile("cp.async.commit_group;");
    }

    // epilogue
#pragma unroll
    for (int ni = 0; ni < 4; ni++) {
        int gc = col0 + wn * 32 + ni * 8 + (lane & 3) * 2;
        float bj0 = bias[gc], bj1 = bias[gc + 1];
#pragma unroll
        for (int mi = 0; mi < 4; mi++) {
            int gr = row0 + wm * 64 + mi * 16 + (lane >> 2);
            float v0 = d[mi][ni][0] + bj0, v1 = d[mi][ni][1] + bj1;
            float v2 = d[mi][ni][2] + bj0, v3 = d[mi][ni][3] + bj1;
            if (RELU) {
                v0 = fmaxf(v0, 0.f); v1 = fmaxf(v1, 0.f);
                v2 = fmaxf(v2, 0.f); v3 = fmaxf(v3, 0.f);
            }
            if (OUT_HALF) {
                __half* Out = (__half*)OutV;
                __half2 h0 = __floats2half2_rn(v0, v1);
                __half2 h1 = __floats2half2_rn(v2, v3);
                if (gr < Nrows)     *(__half2*)&Out[(size_t)gr * O + gc]       = h0;
                if (gr + 8 < Nrows) *(__half2*)&Out[(size_t)(gr + 8) * O + gc] = h1;
            } else {
                float* Out = (float*)OutV;
                if (gr < Nrows)     *(float2*)&Out[(size_t)gr * O + gc]       = make_float2(v0, v1);
                if (gr + 8 < Nrows) *(float2*)&Out[(size_t)(gr + 8) * O + gc] = make_float2(v2, v3);
            }
        }
    }
}

// ---------------------------------------------------------------------------
extern "C" void kernel_launch(void* const* d_in, const int* in_sizes, int n_in,
                              void* d_out, int out_size) {
    const float* x     = (const float*)d_in[0];
    const int*   ei    = (const int*)d_in[1];
    const int*   et    = (const int*)d_in[2];
    const float* W     = (const float*)d_in[3];
    const float* eps   = (const float*)d_in[4];
    const float* A_emb = (const float*)d_in[5];
    const float* B_emb = (const float*)d_in[6];
    const float* W1    = (const float*)d_in[7];
    const float* b1    = (const float*)d_in[8];
    const float* W2    = (const float*)d_in[9];
    const float* b2    = (const float*)d_in[10];
    const float* W3    = (const float*)d_in[11];
    const float* b3    = (const float*)d_in[12];
    float* out = (float*)d_out;

    void *p_out, *p_h1, *p_h2, *p_w1, *p_w2, *p_w3;
    cudaGetSymbolAddress(&p_out, g_out);
    cudaGetSymbolAddress(&p_h1, g_h1);
    cudaGetSymbolAddress(&p_h2, g_h2);
    cudaGetSymbolAddress(&p_w1, g_W1h);
    cudaGetSymbolAddress(&p_w2, g_W2h);
    cudaGetSymbolAddress(&p_w3, g_W3h);

    cudaFuncSetAttribute(k_edge_mma, cudaFuncAttributeMaxDynamicSharedMemorySize, EDGE_SMEM);
    cudaFuncSetAttribute(mlp_mma<true, true, true>,    cudaFuncAttributeMaxDynamicSharedMemorySize, MLP_SMEM);
    cudaFuncSetAttribute(mlp_mma<true, true, false>,   cudaFuncAttributeMaxDynamicSharedMemorySize, MLP_SMEM);
    cudaFuncSetAttribute(mlp_mma<false, false, false>, cudaFuncAttributeMaxDynamicSharedMemorySize, MLP_SMEM);

    // launch index:                                            0
    k_prep<<<PREP_GRID, 256>>>(x, eps, W, A_emb, B_emb, W1, W2, W3, et);
    k_build_tiles<<<1, 256>>>();                             // 1
    k_scatter<<<(EE + 255) / 256, 256>>>(et);                // 2
    k_edge_mma<<<MAXTILES, 256, EDGE_SMEM>>>(x, ei);         // 3  <- ncu captures this
    int gx = (NND + BM - 1) / BM;   // 782
    dim3 g12(gx, H / BN);           // (782, 2)
    mlp_mma<true, true, true><<<g12, 256, MLP_SMEM>>>(p_out, (const __half*)p_w1, b1, p_h1, NND, DD, H);
    mlp_mma<true, true, false><<<g12, 256, MLP_SMEM>>>(p_h1, (const __half*)p_w2, b2, p_h2, NND, H, H);
    dim3 g3(gx, DD / BN);           // (782, 1)
    mlp_mma<false, false, false><<<g3, 256, MLP_SMEM>>>(p_h2, (const __half*)p_w3, b3, out, NND, H, DD);
}

// round 8
// speedup vs baseline: 4.7754x; 1.0587x over previous
#include <cuda_runtime.h>
#include <cuda_fp16.h>
#include <cstdint>

constexpr int NND = 100000;
constexpr int DD  = 128;
constexpr int EE  = 250000;
constexpr int NRL = 16;
constexpr int RR  = 8;
constexpr int H   = 256;
constexpr int TE  = 64;
constexpr int MAXTILES = 4096;
constexpr int CHUNK = 16;       // tiles per index-preload group
constexpr int EDGE_GRID = 444;  // 3 CTAs/SM * 148 SMs

// Static device scratch
__device__ __half g_Mh[NRL * DD * DD];          // fused M^T per relation, fp16, [t][o][i]
__device__ float  g_out[(size_t)NND * DD];      // GIN pre-MLP accumulator (fp32)
__device__ __half g_xh[(size_t)NND * DD];       // fp16 copy of x for edge gather
__device__ __half g_h1[(size_t)NND * H];
__device__ __half g_h2[(size_t)NND * H];
__device__ __half g_W1h[H * DD];
__device__ __half g_W2h[H * H];
__device__ __half g_W3h[DD * H];
__device__ int    g_eids[EE];
__device__ int    g_cnt[NRL];
__device__ int    g_off[NRL + 1];
__device__ int    g_fill[NRL];
__device__ int    g_tiles[MAXTILES * 2];
__device__ int    g_ntiles;

// ---------------------------------------------------------------------------
__device__ __forceinline__ uint32_t smem_u32(const void* p) {
    return (uint32_t)__cvta_generic_to_shared(p);
}
__device__ __forceinline__ void ldsm4(uint32_t* r, uint32_t addr) {
    asm volatile("ldmatrix.sync.aligned.m8n8.x4.shared.b16 {%0,%1,%2,%3}, [%4];"
                 : "=r"(r[0]), "=r"(r[1]), "=r"(r[2]), "=r"(r[3]) : "r"(addr));
}
__device__ __forceinline__ void mma16(float* d, const uint32_t* a, uint32_t b0, uint32_t b1) {
    asm volatile(
        "mma.sync.aligned.m16n8k16.row.col.f32.f16.f16.f32 "
        "{%0,%1,%2,%3},{%4,%5,%6,%7},{%8,%9},{%0,%1,%2,%3};"
        : "+f"(d[0]), "+f"(d[1]), "+f"(d[2]), "+f"(d[3])
        : "r"(a[0]), "r"(a[1]), "r"(a[2]), "r"(a[3]), "r"(b0), "r"(b1));
}
__device__ __forceinline__ void pack8h(uint32_t* o, const float* f) {
#pragma unroll
    for (int i = 0; i < 4; i++) {
        __half2 h = __floats2half2_rn(f[2 * i], f[2 * i + 1]);
        o[i] = *(uint32_t*)&h;
    }
}

// ---------------------------------------------------------------------------
// Fused prep: disjoint block ranges, all independent.
constexpr int PREP_INIT0 = NRL;                       // 16
constexpr int PREP_CVTX0 = PREP_INIT0 + 12500;        // 12516
constexpr int PREP_HIST0 = PREP_CVTX0 + 12500;        // 25016
constexpr int PREP_CVTW0 = PREP_HIST0 + 977;          // 25993
constexpr int PREP_GRID  = PREP_CVTW0 + 256;          // 26249

__global__ void __launch_bounds__(256) k_prep(const float* __restrict__ x,
                                              const float* __restrict__ eps,
                                              const float* __restrict__ W,
                                              const float* __restrict__ A_emb,
                                              const float* __restrict__ B_emb,
                                              const float* __restrict__ W1,
                                              const float* __restrict__ W2,
                                              const float* __restrict__ W3,
                                              const int* __restrict__ et) {
    int b = blockIdx.x;
    if (b < PREP_INIT0) {
        int t = b;
        __shared__ float As[DD * RR];
        __shared__ float Bs[DD * RR];
        for (int i = threadIdx.x; i < DD * RR; i += blockDim.x) {
            As[i] = A_emb[(size_t)t * DD * RR + i];
            Bs[i] = B_emb[(size_t)t * DD * RR + i];
        }
        __syncthreads();
        for (int idx = threadIdx.x; idx < DD * DD; idx += blockDim.x) {
            int o = idx >> 7;
            int i = idx & 127;
            float s = W[o * DD + i];
#pragma unroll
            for (int k = 0; k < RR; k++) s += Bs[i * RR + k] * As[o * RR + k];
            g_Mh[t * DD * DD + o * DD + i] = __float2half_rn(s);
        }
    } else if (b < PREP_CVTX0) {
        // g_out = (1+eps)*x
        float s = 1.0f + eps[0];
        int i = (b - PREP_INIT0) * 256 + threadIdx.x;
        if (i < NND * DD / 4) {
            float4 v = ((const float4*)x)[i];
            v.x *= s; v.y *= s; v.z *= s; v.w *= s;
            ((float4*)g_out)[i] = v;
        }
    } else if (b < PREP_HIST0) {
        // g_xh = fp16(x)
        int i = (b - PREP_CVTX0) * 256 + threadIdx.x;
        if (i < NND * DD / 4) {
            float4 v = ((const float4*)x)[i];
            __half2 h0 = __floats2half2_rn(v.x, v.y);
            __half2 h1 = __floats2half2_rn(v.z, v.w);
            uint2 u; u.x = *(uint32_t*)&h0; u.y = *(uint32_t*)&h1;
            ((uint2*)g_xh)[i] = u;
        }
    } else if (b < PREP_CVTW0) {
        __shared__ int lc[NRL];
        if (threadIdx.x < NRL) lc[threadIdx.x] = 0;
        __syncthreads();
        int e = (b - PREP_HIST0) * 256 + threadIdx.x;
        if (e < EE) {
            int t = et[e];
            if (t >= 0 && t < NRL) atomicAdd(&lc[t], 1);
        }
        __syncthreads();
        if (threadIdx.x < NRL && lc[threadIdx.x]) atomicAdd(&g_cnt[threadIdx.x], lc[threadIdx.x]);
    } else {
        int i = (b - PREP_CVTW0) * 256 + threadIdx.x;
        if (i < H * DD) g_W1h[i] = __float2half_rn(W1[i]);
        if (i < H * H)  g_W2h[i] = __float2half_rn(W2[i]);
        if (i < DD * H) g_W3h[i] = __float2half_rn(W3[i]);
    }
}

__global__ void k_build_tiles() {
    __shared__ int off_s[NRL + 1], tbase[NRL + 1];
    if (threadIdx.x == 0) {
        int acc = 0;
        for (int t = 0; t < NRL; t++) { off_s[t] = acc; acc += g_cnt[t]; }
        off_s[NRL] = acc;
        int tb = 0;
        for (int t = 0; t < NRL; t++) { tbase[t] = tb; tb += (g_cnt[t] + TE - 1) / TE; }
        tbase[NRL] = tb;
        for (int t = 0; t <= NRL; t++) g_off[t] = off_s[t];
        g_ntiles = tb;
    }
    __syncthreads();
    if (threadIdx.x < NRL) g_cnt[threadIdx.x] = 0;   // self-zero for next replay
    for (int s = threadIdx.x; s < MAXTILES; s += blockDim.x) {
        int t = -1, e0 = 0;
        for (int tt = 0; tt < NRL; tt++) {
            if (s >= tbase[tt] && s < tbase[tt + 1]) {
                t = tt;
                e0 = off_s[tt] + (s - tbase[tt]) * TE;
            }
        }
        g_tiles[2 * s] = t;
        g_tiles[2 * s + 1] = e0;
    }
}

__global__ void k_scatter(const int* __restrict__ et) {
    __shared__ int lc[NRL], lbase[NRL], lfill[NRL];
    if (threadIdx.x < NRL) { lc[threadIdx.x] = 0; lfill[threadIdx.x] = 0; }
    __syncthreads();
    int e = blockIdx.x * blockDim.x + threadIdx.x;
    int t = -1;
    if (e < EE) {
        t = et[e];
        if (t >= 0 && t < NRL) atomicAdd(&lc[t], 1); else t = -1;
    }
    __syncthreads();
    if (threadIdx.x < NRL && lc[threadIdx.x])
        lbase[threadIdx.x] = atomicAdd(&g_fill[threadIdx.x], lc[threadIdx.x]);
    __syncthreads();
    if (t >= 0) {
        int p = atomicAdd(&lfill[t], 1);
        g_eids[g_off[t] + lbase[t] + p] = e;
    }
}

// ---------------------------------------------------------------------------
// Persistent edge GEMM: 444 CTAs, each owns a contiguous tile range (sorted
// by relation). M loaded only on relation change; X gathered fp16 via
// cp.async, double-buffered; red.v2 scatter from fragments.
// smem: M 32KB | X 2x16KB | idx 8KB = 73728 B -> 3 CTAs/SM.
constexpr int EDGE_SMEM = 32768 + 32768 + CHUNK * TE * 2 * 4;

__global__ void __launch_bounds__(256, 3) k_edge_mma(const __half* __restrict__ xh,
                                                     const int* __restrict__ ei) {
    extern __shared__ char smc[];
    __half* Ms = (__half*)smc;                  // [0, 32768)
    char* Xb = smc + 32768;                     // two 16KB buffers
    int* srcsA = (int*)(smc + 65536);           // CHUNK*64 ints
    int* dstsA = srcsA + CHUNK * TE;
    int tid = threadIdx.x;

    if (blockIdx.x < NRL && tid == 0) g_fill[blockIdx.x] = 0;  // reset for next replay

    int nt = g_ntiles;
    int per = (nt + gridDim.x - 1) / gridDim.x;
    int i0 = blockIdx.x * per;
    int i1 = min(i0 + per, nt);
    if (i0 >= i1) return;

    int lane = tid & 31, w = tid >> 5;
    int wm = w & 1, wn = w >> 1;
    int arow0 = wm * 32 + (lane & 15);
    int brow0 = wn * 32 + (lane & 15);
    uint32_t ms_base = smem_u32(Ms);
    int cur_rel = -1;

    auto gather = [&](int k) {   // async-gather tile k (within group) into buf k&1
        char* xb = Xb + (k & 1) * 16384;
        const int* sp = srcsA + k * TE;
        uint32_t xb32 = smem_u32(xb);
#pragma unroll
        for (int i = 0; i < 4; i++) {
            int l = tid + i * 256;
            int r = l >> 4, u = l & 15;
            int s = sp[r];
            bool pa = s >= 0;
            const __half* src = pa ? (xh + (size_t)s * DD + u * 8) : xh;
            uint32_t dst = xb32 + (uint32_t)((r * 16 + (u ^ (r & 7))) * 16);
            asm volatile("cp.async.ca.shared.global [%0], [%1], 16, %2;"
                         :: "r"(dst), "l"(src), "r"(pa ? 16 : 0));
        }
        asm volatile("cp.async.commit_group;");
    };

    for (int gbase = i0; gbase < i1; gbase += CHUNK) {
        int gc = min(CHUNK, i1 - gbase);

        // batched index preload for this group
        for (int l = tid; l < gc * TE; l += 256) {
            int ti = gbase + (l >> 6), j = l & 63;
            int tt = g_tiles[2 * ti];
            int e0 = g_tiles[2 * ti + 1];
            int cnt = g_off[tt + 1] - e0;
            int s = -1, d = -1;
            if (j < cnt) {
                int e = g_eids[e0 + j];
                s = ei[e];
                d = ei[EE + e];
                if (s < 0 || s >= NND) s = -1;
                if (d < 0 || d >= NND) d = -1;
            }
            srcsA[l] = s;
            dstsA[l] = d;
        }
        __syncthreads();

        gather(0);
        for (int k = 0; k < gc; k++) {
            if (k + 1 < gc) {
                gather(k + 1);
                asm volatile("cp.async.wait_group 1;");
            } else {
                asm volatile("cp.async.wait_group 0;");
            }
            __syncthreads();

            int t = g_tiles[2 * (gbase + k)];
            if (t != cur_rel) {
                const uint4* Msrc = (const uint4*)(g_Mh + (size_t)t * DD * DD);
#pragma unroll
                for (int j = 0; j < 8; j++) {
                    int l = tid + j * 256;
                    int r = l >> 4, u = l & 15;
                    uint4 v = Msrc[l];
                    *(uint4*)((char*)Ms + (r * 16 + (u ^ (r & 7))) * 16) = v;
                }
                cur_rel = t;
                __syncthreads();
            }

            uint32_t xs_base = smem_u32(Xb + (k & 1) * 16384);
            float d[2][4][4];
#pragma unroll
            for (int mi = 0; mi < 2; mi++)
#pragma unroll
                for (int ni = 0; ni < 4; ni++)
#pragma unroll
                    for (int c = 0; c < 4; c++) d[mi][ni][c] = 0.f;

#pragma unroll
            for (int ks = 0; ks < 8; ks++) {
                int uu = ks * 2 + (lane >> 4);
                uint32_t a[2][4], b[2][4];
#pragma unroll
                for (int mi = 0; mi < 2; mi++) {
                    int r = arow0 + mi * 16;
                    ldsm4(a[mi], xs_base + (uint32_t)((r * 16 + (uu ^ (r & 7))) * 16));
                }
#pragma unroll
                for (int pp = 0; pp < 2; pp++) {
                    int r = brow0 + pp * 16;
                    ldsm4(b[pp], ms_base + (uint32_t)((r * 16 + (uu ^ (r & 7))) * 16));
                }
#pragma unroll
                for (int mi = 0; mi < 2; mi++)
#pragma unroll
                    for (int ni = 0; ni < 4; ni++) {
                        int pp = ni >> 1, o = ni & 1;
                        mma16(d[mi][ni], a[mi], b[pp][o], b[pp][2 + o]);
                    }
            }

            const int* dp = dstsA + k * TE;
            int ocb = wn * 32 + (lane & 3) * 2;
#pragma unroll
            for (int mi = 0; mi < 2; mi++) {
                int er = wm * 32 + mi * 16 + (lane >> 2);
                int d0 = dp[er];
                int d1 = dp[er + 8];
#pragma unroll
                for (int ni = 0; ni < 4; ni++) {
                    int oc = ocb + ni * 8;
                    if (d0 >= 0) {
                        float* p = g_out + (size_t)d0 * DD + oc;
                        asm volatile("red.global.add.v2.f32 [%0], {%1,%2};"
                                     :: "l"(p), "f"(d[mi][ni][0]), "f"(d[mi][ni][1]) : "memory");
                    }
                    if (d1 >= 0) {
                        float* p = g_out + (size_t)d1 * DD + oc;
                        asm volatile("red.global.add.v2.f32 [%0], {%1,%2};"
                                     :: "l"(p), "f"(d[mi][ni][2]), "f"(d[mi][ni][3]) : "memory");
                    }
                }
            }
            __syncthreads();
        }
    }
}

// ---------------------------------------------------------------------------
// MLP GEMM via fp16 mma.sync (unchanged from R7).
constexpr int BM = 128, BN = 128, BKH = 64, NSTG = 3;
constexpr int STAGE_A = BM * BKH;
constexpr int STAGE_B = BN * BKH;
constexpr int MLP_SMEM = NSTG * (STAGE_A + STAGE_B) * 2;   // 98304

template <bool RELU, bool OUT_HALF, bool IN_FLOAT>
__global__ void __launch_bounds__(256, 2) mlp_mma(const void* __restrict__ InV,
                                                  const __half* __restrict__ Wt,
                                                  const float* __restrict__ bias,
                                                  void* __restrict__ OutV,
                                                  int Nrows, int K, int O) {
    extern __shared__ char smc[];
    __half* Abuf = (__half*)smc;
    __half* Bbuf = Abuf + NSTG * STAGE_A;
    int tid = threadIdx.x, lane = tid & 31, w = tid >> 5;
    int row0 = blockIdx.x * BM, col0 = blockIdx.y * BN;
    int kt = K / BKH;

    auto issue = [&](int s) {
        int buf = s % NSTG;
        uint32_t abase = smem_u32(Abuf + buf * STAGE_A);
        uint32_t bbase = smem_u32(Bbuf + buf * STAGE_B);
        int k0 = s * BKH;
#pragma unroll
        for (int i = 0; i < 4; i++) {
            int l = tid + i * 256;
            int r = l >> 3, u = l & 7;
            int gr = row0 + r;
            bool pa = gr < Nrows;
            if (IN_FLOAT) {
                const float* In = (const float*)InV;
                float f[8];
                if (pa) {
                    const float4* src = (const float4*)(In + (size_t)gr * K + k0 + u * 8);
                    float4 a = src[0], b = src[1];
                    f[0]=a.x; f[1]=a.y; f[2]=a.z; f[3]=a.w;
                    f[4]=b.x; f[5]=b.y; f[6]=b.z; f[7]=b.w;
                } else {
#pragma unroll
                    for (int q = 0; q < 8; q++) f[q] = 0.f;
                }
                uint32_t h[4];
                pack8h(h, f);
                *(uint4*)(Abuf + buf * STAGE_A + (r * 8 + (u ^ (r & 7))) * 8) =
                    make_uint4(h[0], h[1], h[2], h[3]);
            } else {
                const __half* In = (const __half*)InV;
                const __half* srcA = pa ? (In + (size_t)gr * K + k0 + u * 8) : In;
                uint32_t da = abase + (uint32_t)((r * 8 + (u ^ (r & 7))) * 16);
                asm volatile("cp.async.ca.shared.global [%0], [%1], 16, %2;"
                             :: "r"(da), "l"(srcA), "r"(pa ? 16 : 0));
            }
            const __half* srcB = Wt + (size_t)(col0 + r) * K + k0 + u * 8;
            uint32_t db = bbase + (uint32_t)((r * 8 + (u ^ (r & 7))) * 16);
            asm volatile("cp.async.ca.shared.global [%0], [%1], 16, %2;"
                         :: "r"(db), "l"(srcB), "r"(16));
        }
    };

    int wm = w & 1, wn = w >> 1;
    int arow0 = wm * 64 + (lane & 15);
    int brow0 = wn * 32 + (lane & 15);

    float d[4][4][4];
#pragma unroll
    for (int mi = 0; mi < 4; mi++)
#pragma unroll
        for (int ni = 0; ni < 4; ni++)
#pragma unroll
            for (int c = 0; c < 4; c++) d[mi][ni][c] = 0.f;

    issue(0);               asm volatile("cp.async.commit_group;");
    if (kt > 1) issue(1);   asm volatile("cp.async.commit_group;");

    for (int s = 0; s < kt; s++) {
        asm volatile("cp.async.wait_group %0;" :: "n"(1));
        __syncthreads();
        int buf = s % NSTG;
        uint32_t abase = smem_u32(Abuf + buf * STAGE_A);
        uint32_t bbase = smem_u32(Bbuf + buf * STAGE_B);

#pragma unroll
        for (int ks = 0; ks < 4; ks++) {
            int uu = ks * 2 + (lane >> 4);
            uint32_t a[4][4], b[2][4];
#pragma unroll
            for (int mi = 0; mi < 4; mi++) {
                int r = arow0 + mi * 16;
                ldsm4(a[mi], abase + (uint32_t)((r * 8 + (uu ^ (r & 7))) * 16));
            }
#pragma unroll
            for (int pp = 0; pp < 2; pp++) {
                int r = brow0 + pp * 16;
                ldsm4(b[pp], bbase + (uint32_t)((r * 8 + (uu ^ (r & 7))) * 16));
            }
#pragma unroll
            for (int mi = 0; mi < 4; mi++)
#pragma unroll
                for (int ni = 0; ni < 4; ni++) {
                    int pp = ni >> 1, o = ni & 1;
                    mma16(d[mi][ni], a[mi], b[pp][o], b[pp][2 + o]);
                }
        }
        if (s + 2 < kt) issue(s + 2);
        asm volatile("cp.async.commit_group;");
    }

#pragma unroll
    for (int ni = 0; ni < 4; ni++) {
        int gc = col0 + wn * 32 + ni * 8 + (lane & 3) * 2;
        float bj0 = bias[gc], bj1 = bias[gc + 1];
#pragma unroll
        for (int mi = 0; mi < 4; mi++) {
            int gr = row0 + wm * 64 + mi * 16 + (lane >> 2);
            float v0 = d[mi][ni][0] + bj0, v1 = d[mi][ni][1] + bj1;
            float v2 = d[mi][ni][2] + bj0, v3 = d[mi][ni][3] + bj1;
            if (RELU) {
                v0 = fmaxf(v0, 0.f); v1 = fmaxf(v1, 0.f);
                v2 = fmaxf(v2, 0.f); v3 = fmaxf(v3, 0.f);
            }
            if (OUT_HALF) {
                __half* Out = (__half*)OutV;
                __half2 h0 = __floats2half2_rn(v0, v1);
                __half2 h1 = __floats2half2_rn(v2, v3);
                if (gr < Nrows)     *(__half2*)&Out[(size_t)gr * O + gc]       = h0;
                if (gr + 8 < Nrows) *(__half2*)&Out[(size_t)(gr + 8) * O + gc] = h1;
            } else {
                float* Out = (float*)OutV;
                if (gr < Nrows)     *(float2*)&Out[(size_t)gr * O + gc]       = make_float2(v0, v1);
                if (gr + 8 < Nrows) *(float2*)&Out[(size_t)(gr + 8) * O + gc] = make_float2(v2, v3);
            }
        }
    }
}

// ---------------------------------------------------------------------------
extern "C" void kernel_launch(void* const* d_in, const int* in_sizes, int n_in,
                              void* d_out, int out_size) {
    const float* x     = (const float*)d_in[0];
    const int*   ei    = (const int*)d_in[1];
    const int*   et    = (const int*)d_in[2];
    const float* W     = (const float*)d_in[3];
    const float* eps   = (const float*)d_in[4];
    const float* A_emb = (const float*)d_in[5];
    const float* B_emb = (const float*)d_in[6];
    const float* W1    = (const float*)d_in[7];
    const float* b1    = (const float*)d_in[8];
    const float* W2    = (const float*)d_in[9];
    const float* b2    = (const float*)d_in[10];
    const float* W3    = (const float*)d_in[11];
    const float* b3    = (const float*)d_in[12];
    float* out = (float*)d_out;

    void *p_out, *p_xh, *p_h1, *p_h2, *p_w1, *p_w2, *p_w3;
    cudaGetSymbolAddress(&p_out, g_out);
    cudaGetSymbolAddress(&p_xh, g_xh);
    cudaGetSymbolAddress(&p_h1, g_h1);
    cudaGetSymbolAddress(&p_h2, g_h2);
    cudaGetSymbolAddress(&p_w1, g_W1h);
    cudaGetSymbolAddress(&p_w2, g_W2h);
    cudaGetSymbolAddress(&p_w3, g_W3h);

    cudaFuncSetAttribute(k_edge_mma, cudaFuncAttributeMaxDynamicSharedMemorySize, EDGE_SMEM);
    cudaFuncSetAttribute(mlp_mma<true, true, true>,    cudaFuncAttributeMaxDynamicSharedMemorySize, MLP_SMEM);
    cudaFuncSetAttribute(mlp_mma<true, true, false>,   cudaFuncAttributeMaxDynamicSharedMemorySize, MLP_SMEM);
    cudaFuncSetAttribute(mlp_mma<false, false, false>, cudaFuncAttributeMaxDynamicSharedMemorySize, MLP_SMEM);

    // launch index:                                            0
    k_prep<<<PREP_GRID, 256>>>(x, eps, W, A_emb, B_emb, W1, W2, W3, et);
    k_build_tiles<<<1, 256>>>();                             // 1
    k_scatter<<<(EE + 255) / 256, 256>>>(et);                // 2
    k_edge_mma<<<EDGE_GRID, 256, EDGE_SMEM>>>((const __half*)p_xh, ei);  // 3 <- profiled
    int gx = (NND + BM - 1) / BM;   // 782
    dim3 g12(gx, H / BN);           // (782, 2)
    mlp_mma<true, true, true><<<g12, 256, MLP_SMEM>>>(p_out, (const __half*)p_w1, b1, p_h1, NND, DD, H);
    mlp_mma<true, true, false><<<g12, 256, MLP_SMEM>>>(p_h1, (const __half*)p_w2, b2, p_h2, NND, H, H);
    dim3 g3(gx, DD / BN);           // (782, 1)
    mlp_mma<false, false, false><<<g3, 256, MLP_SMEM>>>(p_h2, (const __half*)p_w3, b3, out, NND, H, DD);
}

// round 9
// speedup vs baseline: 4.8845x; 1.0228x over previous
#include <cuda_runtime.h>
#include <cuda_fp16.h>
#include <cstdint>

constexpr int NND = 100000;
constexpr int DD  = 128;
constexpr int EE  = 250000;
constexpr int NRL = 16;
constexpr int RR  = 8;
constexpr int H   = 256;
constexpr int TE  = 64;
constexpr int MAXTILES = 4096;
constexpr int CHUNK = 16;
constexpr int EDGE_GRID = 444;

// Static device scratch
__device__ __half g_Mh[NRL * DD * DD];
__device__ float  g_out[(size_t)NND * DD];
__device__ __half g_xh[(size_t)NND * DD];
__device__ __half g_h1[(size_t)NND * H];
__device__ __half g_h2[(size_t)NND * H];
__device__ __half g_W1h[H * DD];
__device__ __half g_W2h[H * H];
__device__ __half g_W3h[DD * H];
__device__ int    g_eids[EE];
__device__ int    g_cnt[NRL];
__device__ int    g_off[NRL + 1];
__device__ int    g_fill[NRL];
__device__ int    g_tiles[MAXTILES * 2];
__device__ int    g_ntiles;

// ---------------------------------------------------------------------------
__device__ __forceinline__ uint32_t smem_u32(const void* p) {
    return (uint32_t)__cvta_generic_to_shared(p);
}
__device__ __forceinline__ void ldsm4(uint32_t* r, uint32_t addr) {
    asm volatile("ldmatrix.sync.aligned.m8n8.x4.shared.b16 {%0,%1,%2,%3}, [%4];"
                 : "=r"(r[0]), "=r"(r[1]), "=r"(r[2]), "=r"(r[3]) : "r"(addr));
}
__device__ __forceinline__ void mma16(float* d, const uint32_t* a, uint32_t b0, uint32_t b1) {
    asm volatile(
        "mma.sync.aligned.m16n8k16.row.col.f32.f16.f16.f32 "
        "{%0,%1,%2,%3},{%4,%5,%6,%7},{%8,%9},{%0,%1,%2,%3};"
        : "+f"(d[0]), "+f"(d[1]), "+f"(d[2]), "+f"(d[3])
        : "r"(a[0]), "r"(a[1]), "r"(a[2]), "r"(a[3]), "r"(b0), "r"(b1));
}
__device__ __forceinline__ void pack8h(uint32_t* o, const float* f) {
#pragma unroll
    for (int i = 0; i < 4; i++) {
        __half2 h = __floats2half2_rn(f[2 * i], f[2 * i + 1]);
        o[i] = *(uint32_t*)&h;
    }
}

// ---------------------------------------------------------------------------
// Fused prep: [0,16) build_M, [16,12516) init_out+cvt_x (x read ONCE),
// [12516,13493) hist, [13493,13749) cvt_w.
constexpr int PREP_INIT0 = NRL;                       // 16
constexpr int PREP_HIST0 = PREP_INIT0 + 12500;        // 12516
constexpr int PREP_CVTW0 = PREP_HIST0 + 977;          // 13493
constexpr int PREP_GRID  = PREP_CVTW0 + 256;          // 13749

__global__ void __launch_bounds__(256) k_prep(const float* __restrict__ x,
                                              const float* __restrict__ eps,
                                              const float* __restrict__ W,
                                              const float* __restrict__ A_emb,
                                              const float* __restrict__ B_emb,
                                              const float* __restrict__ W1,
                                              const float* __restrict__ W2,
                                              const float* __restrict__ W3,
                                              const int* __restrict__ et) {
    int b = blockIdx.x;
    if (b < PREP_INIT0) {
        int t = b;
        __shared__ float As[DD * RR];
        __shared__ float Bs[DD * RR];
        for (int i = threadIdx.x; i < DD * RR; i += blockDim.x) {
            As[i] = A_emb[(size_t)t * DD * RR + i];
            Bs[i] = B_emb[(size_t)t * DD * RR + i];
        }
        __syncthreads();
        for (int idx = threadIdx.x; idx < DD * DD; idx += blockDim.x) {
            int o = idx >> 7;
            int i = idx & 127;
            float s = W[o * DD + i];
#pragma unroll
            for (int k = 0; k < RR; k++) s += Bs[i * RR + k] * As[o * RR + k];
            g_Mh[t * DD * DD + o * DD + i] = __float2half_rn(s);
        }
    } else if (b < PREP_HIST0) {
        // read x once -> g_out = (1+eps)*x  AND  g_xh = fp16(x)
        float s = 1.0f + eps[0];
        int i = (b - PREP_INIT0) * 256 + threadIdx.x;
        if (i < NND * DD / 4) {
            float4 v = ((const float4*)x)[i];
            __half2 h0 = __floats2half2_rn(v.x, v.y);
            __half2 h1 = __floats2half2_rn(v.z, v.w);
            uint2 u; u.x = *(uint32_t*)&h0; u.y = *(uint32_t*)&h1;
            ((uint2*)g_xh)[i] = u;
            v.x *= s; v.y *= s; v.z *= s; v.w *= s;
            ((float4*)g_out)[i] = v;
        }
    } else if (b < PREP_CVTW0) {
        __shared__ int lc[NRL];
        if (threadIdx.x < NRL) lc[threadIdx.x] = 0;
        __syncthreads();
        int e = (b - PREP_HIST0) * 256 + threadIdx.x;
        if (e < EE) {
            int t = et[e];
            if (t >= 0 && t < NRL) atomicAdd(&lc[t], 1);
        }
        __syncthreads();
        if (threadIdx.x < NRL && lc[threadIdx.x]) atomicAdd(&g_cnt[threadIdx.x], lc[threadIdx.x]);
    } else {
        int i = (b - PREP_CVTW0) * 256 + threadIdx.x;
        if (i < H * DD) g_W1h[i] = __float2half_rn(W1[i]);
        if (i < H * H)  g_W2h[i] = __float2half_rn(W2[i]);
        if (i < DD * H) g_W3h[i] = __float2half_rn(W3[i]);
    }
}

__global__ void k_build_tiles() {
    __shared__ int off_s[NRL + 1], tbase[NRL + 1];
    if (threadIdx.x == 0) {
        int acc = 0;
        for (int t = 0; t < NRL; t++) { off_s[t] = acc; acc += g_cnt[t]; }
        off_s[NRL] = acc;
        int tb = 0;
        for (int t = 0; t < NRL; t++) { tbase[t] = tb; tb += (g_cnt[t] + TE - 1) / TE; }
        tbase[NRL] = tb;
        for (int t = 0; t <= NRL; t++) g_off[t] = off_s[t];
        g_ntiles = tb;
    }
    __syncthreads();
    if (threadIdx.x < NRL) g_cnt[threadIdx.x] = 0;
    for (int s = threadIdx.x; s < MAXTILES; s += blockDim.x) {
        int t = -1, e0 = 0;
        for (int tt = 0; tt < NRL; tt++) {
            if (s >= tbase[tt] && s < tbase[tt + 1]) {
                t = tt;
                e0 = off_s[tt] + (s - tbase[tt]) * TE;
            }
        }
        g_tiles[2 * s] = t;
        g_tiles[2 * s + 1] = e0;
    }
}

__global__ void k_scatter(const int* __restrict__ et) {
    __shared__ int lc[NRL], lbase[NRL], lfill[NRL];
    if (threadIdx.x < NRL) { lc[threadIdx.x] = 0; lfill[threadIdx.x] = 0; }
    __syncthreads();
    int e = blockIdx.x * blockDim.x + threadIdx.x;
    int t = -1;
    if (e < EE) {
        t = et[e];
        if (t >= 0 && t < NRL) atomicAdd(&lc[t], 1); else t = -1;
    }
    __syncthreads();
    if (threadIdx.x < NRL && lc[threadIdx.x])
        lbase[threadIdx.x] = atomicAdd(&g_fill[threadIdx.x], lc[threadIdx.x]);
    __syncthreads();
    if (t >= 0) {
        int p = atomicAdd(&lfill[t], 1);
        g_eids[g_off[t] + lbase[t] + p] = e;
    }
}

// ---------------------------------------------------------------------------
// Persistent edge GEMM (unchanged from R8)
constexpr int EDGE_SMEM = 32768 + 32768 + CHUNK * TE * 2 * 4;

__global__ void __launch_bounds__(256, 3) k_edge_mma(const __half* __restrict__ xh,
                                                     const int* __restrict__ ei) {
    extern __shared__ char smc[];
    __half* Ms = (__half*)smc;
    char* Xb = smc + 32768;
    int* srcsA = (int*)(smc + 65536);
    int* dstsA = srcsA + CHUNK * TE;
    int tid = threadIdx.x;

    if (blockIdx.x < NRL && tid == 0) g_fill[blockIdx.x] = 0;

    int nt = g_ntiles;
    int per = (nt + gridDim.x - 1) / gridDim.x;
    int i0 = blockIdx.x * per;
    int i1 = min(i0 + per, nt);
    if (i0 >= i1) return;

    int lane = tid & 31, w = tid >> 5;
    int wm = w & 1, wn = w >> 1;
    int arow0 = wm * 32 + (lane & 15);
    int brow0 = wn * 32 + (lane & 15);
    uint32_t ms_base = smem_u32(Ms);
    int cur_rel = -1;

    auto gather = [&](int k) {
        char* xb = Xb + (k & 1) * 16384;
        const int* sp = srcsA + k * TE;
        uint32_t xb32 = smem_u32(xb);
#pragma unroll
        for (int i = 0; i < 4; i++) {
            int l = tid + i * 256;
            int r = l >> 4, u = l & 15;
            int s = sp[r];
            bool pa = s >= 0;
            const __half* src = pa ? (xh + (size_t)s * DD + u * 8) : xh;
            uint32_t dst = xb32 + (uint32_t)((r * 16 + (u ^ (r & 7))) * 16);
            asm volatile("cp.async.ca.shared.global [%0], [%1], 16, %2;"
                         :: "r"(dst), "l"(src), "r"(pa ? 16 : 0));
        }
        asm volatile("cp.async.commit_group;");
    };

    for (int gbase = i0; gbase < i1; gbase += CHUNK) {
        int gc = min(CHUNK, i1 - gbase);

        for (int l = tid; l < gc * TE; l += 256) {
            int ti = gbase + (l >> 6), j = l & 63;
            int tt = g_tiles[2 * ti];
            int e0 = g_tiles[2 * ti + 1];
            int cnt = g_off[tt + 1] - e0;
            int s = -1, d = -1;
            if (j < cnt) {
                int e = g_eids[e0 + j];
                s = ei[e];
                d = ei[EE + e];
                if (s < 0 || s >= NND) s = -1;
                if (d < 0 || d >= NND) d = -1;
            }
            srcsA[l] = s;
            dstsA[l] = d;
        }
        __syncthreads();

        gather(0);
        for (int k = 0; k < gc; k++) {
            if (k + 1 < gc) {
                gather(k + 1);
                asm volatile("cp.async.wait_group 1;");
            } else {
                asm volatile("cp.async.wait_group 0;");
            }
            __syncthreads();

            int t = g_tiles[2 * (gbase + k)];
            if (t != cur_rel) {
                const uint4* Msrc = (const uint4*)(g_Mh + (size_t)t * DD * DD);
#pragma unroll
                for (int j = 0; j < 8; j++) {
                    int l = tid + j * 256;
                    int r = l >> 4, u = l & 15;
                    uint4 v = Msrc[l];
                    *(uint4*)((char*)Ms + (r * 16 + (u ^ (r & 7))) * 16) = v;
                }
                cur_rel = t;
                __syncthreads();
            }

            uint32_t xs_base = smem_u32(Xb + (k & 1) * 16384);
            float d[2][4][4];
#pragma unroll
            for (int mi = 0; mi < 2; mi++)
#pragma unroll
                for (int ni = 0; ni < 4; ni++)
#pragma unroll
                    for (int c = 0; c < 4; c++) d[mi][ni][c] = 0.f;

#pragma unroll
            for (int ks = 0; ks < 8; ks++) {
                int uu = ks * 2 + (lane >> 4);
                uint32_t a[2][4], b[2][4];
#pragma unroll
                for (int mi = 0; mi < 2; mi++) {
                    int r = arow0 + mi * 16;
                    ldsm4(a[mi], xs_base + (uint32_t)((r * 16 + (uu ^ (r & 7))) * 16));
                }
#pragma unroll
                for (int pp = 0; pp < 2; pp++) {
                    int r = brow0 + pp * 16;
                    ldsm4(b[pp], ms_base + (uint32_t)((r * 16 + (uu ^ (r & 7))) * 16));
                }
#pragma unroll
                for (int mi = 0; mi < 2; mi++)
#pragma unroll
                    for (int ni = 0; ni < 4; ni++) {
                        int pp = ni >> 1, o = ni & 1;
                        mma16(d[mi][ni], a[mi], b[pp][o], b[pp][2 + o]);
                    }
            }

            const int* dp = dstsA + k * TE;
            int ocb = wn * 32 + (lane & 3) * 2;
#pragma unroll
            for (int mi = 0; mi < 2; mi++) {
                int er = wm * 32 + mi * 16 + (lane >> 2);
                int d0 = dp[er];
                int d1 = dp[er + 8];
#pragma unroll
                for (int ni = 0; ni < 4; ni++) {
                    int oc = ocb + ni * 8;
                    if (d0 >= 0) {
                        float* p = g_out + (size_t)d0 * DD + oc;
                        asm volatile("red.global.add.v2.f32 [%0], {%1,%2};"
                                     :: "l"(p), "f"(d[mi][ni][0]), "f"(d[mi][ni][1]) : "memory");
                    }
                    if (d1 >= 0) {
                        float* p = g_out + (size_t)d1 * DD + oc;
                        asm volatile("red.global.add.v2.f32 [%0], {%1,%2};"
                                     :: "l"(p), "f"(d[mi][ni][2]), "f"(d[mi][ni][3]) : "memory");
                    }
                }
            }
            __syncthreads();
        }
    }
}

// ---------------------------------------------------------------------------
// Wide MLP GEMM (layers 1-2): BM=64, BN=256 (full output width -> input read
// once), BK=64 halves, NSTG=2 double-buffered cp.async, 256 threads,
// warp tile 32x64, 2 CTAs/SM (80KB smem, <=128 regs).
constexpr int WBM = 64, WBN = 256, WBK = 64;
constexpr int WSA = WBM * WBK;   // halves per A stage (8KB)
constexpr int WSB = WBN * WBK;   // halves per B stage (32KB)
constexpr int WIDE_SMEM = 2 * (WSA + WSB) * 2;   // 81920

template <bool RELU, bool IN_FLOAT>
__global__ void __launch_bounds__(256, 2) mlp_wide(const void* __restrict__ InV,
                                                   const __half* __restrict__ Wt,
                                                   const float* __restrict__ bias,
                                                   __half* __restrict__ Out,
                                                   int Nrows, int K) {
    extern __shared__ char smc[];
    __half* Abuf = (__half*)smc;                 // [2][WSA]
    __half* Bbuf = Abuf + 2 * WSA;               // [2][WSB]
    int tid = threadIdx.x, lane = tid & 31, w = tid >> 5;
    int row0 = blockIdx.x * WBM;
    int kt = K / WBK;

    auto issue = [&](int s) {
        int buf = s & 1;
        uint32_t bbase = smem_u32(Bbuf + buf * WSB);
        int k0 = s * WBK;
        // A: 512 16B-units, 2 per thread
#pragma unroll
        for (int i = 0; i < 2; i++) {
            int l = tid + i * 256;
            int r = l >> 3, u = l & 7;
            int gr = row0 + r;
            bool pa = gr < Nrows;
            if (IN_FLOAT) {
                const float* In = (const float*)InV;
                float f[8];
                if (pa) {
                    const float4* src = (const float4*)(In + (size_t)gr * K + k0 + u * 8);
                    float4 a = src[0], b = src[1];
                    f[0]=a.x; f[1]=a.y; f[2]=a.z; f[3]=a.w;
                    f[4]=b.x; f[5]=b.y; f[6]=b.z; f[7]=b.w;
                } else {
#pragma unroll
                    for (int q = 0; q < 8; q++) f[q] = 0.f;
                }
                uint32_t h[4];
                pack8h(h, f);
                *(uint4*)(Abuf + buf * WSA + (r * 8 + (u ^ (r & 7))) * 8) =
                    make_uint4(h[0], h[1], h[2], h[3]);
            } else {
                const __half* In = (const __half*)InV;
                const __half* src = pa ? (In + (size_t)gr * K + k0 + u * 8) : In;
                uint32_t dst = smem_u32(Abuf + buf * WSA) +
                               (uint32_t)((r * 8 + (u ^ (r & 7))) * 16);
                asm volatile("cp.async.ca.shared.global [%0], [%1], 16, %2;"
                             :: "r"(dst), "l"(src), "r"(pa ? 16 : 0));
            }
        }
        // B: 2048 16B-units, 8 per thread
#pragma unroll
        for (int i = 0; i < 8; i++) {
            int l = tid + i * 256;
            int r = l >> 3, u = l & 7;
            const __half* src = Wt + (size_t)r * K + k0 + u * 8;
            uint32_t dst = bbase + (uint32_t)((r * 8 + (u ^ (r & 7))) * 16);
            asm volatile("cp.async.ca.shared.global [%0], [%1], 16, %2;"
                         :: "r"(dst), "l"(src), "r"(16));
        }
        asm volatile("cp.async.commit_group;");
    };

    int wm = w & 1, wn = w >> 1;         // warp tile: 32 rows x 64 cols
    int arow0 = wm * 32 + (lane & 15);
    int brow0 = wn * 64 + (lane & 15);

    float d[2][8][4];
#pragma unroll
    for (int mi = 0; mi < 2; mi++)
#pragma unroll
        for (int nj = 0; nj < 8; nj++)
#pragma unroll
            for (int c = 0; c < 4; c++) d[mi][nj][c] = 0.f;

    issue(0);

    for (int s = 0; s < kt; s++) {
        asm volatile("cp.async.wait_group 0;");
        __syncthreads();
        if (s + 1 < kt) issue(s + 1);
        int buf = s & 1;
        uint32_t abase = smem_u32(Abuf + buf * WSA);
        uint32_t bbase = smem_u32(Bbuf + buf * WSB);
#pragma unroll
        for (int ks = 0; ks < 4; ks++) {
            int uu = ks * 2 + (lane >> 4);
            uint32_t a[2][4], b[4][4];
#pragma unroll
            for (int mi = 0; mi < 2; mi++) {
                int r = arow0 + mi * 16;
                ldsm4(a[mi], abase + (uint32_t)((r * 8 + (uu ^ (r & 7))) * 16));
            }
#pragma unroll
            for (int pp = 0; pp < 4; pp++) {
                int r = brow0 + pp * 16;
                ldsm4(b[pp], bbase + (uint32_t)((r * 8 + (uu ^ (r & 7))) * 16));
            }
#pragma unroll
            for (int mi = 0; mi < 2; mi++)
#pragma unroll
                for (int nj = 0; nj < 8; nj++) {
                    int pp = nj >> 1, o = nj & 1;
                    mma16(d[mi][nj], a[mi], b[pp][o], b[pp][2 + o]);
                }
        }
    }

    // epilogue: bias + relu + fp16 store
#pragma unroll
    for (int nj = 0; nj < 8; nj++) {
        int gc = wn * 64 + nj * 8 + (lane & 3) * 2;
        float bj0 = bias[gc], bj1 = bias[gc + 1];
#pragma unroll
        for (int mi = 0; mi < 2; mi++) {
            int gr = row0 + wm * 32 + mi * 16 + (lane >> 2);
            float v0 = d[mi][nj][0] + bj0, v1 = d[mi][nj][1] + bj1;
            float v2 = d[mi][nj][2] + bj0, v3 = d[mi][nj][3] + bj1;
            if (RELU) {
                v0 = fmaxf(v0, 0.f); v1 = fmaxf(v1, 0.f);
                v2 = fmaxf(v2, 0.f); v3 = fmaxf(v3, 0.f);
            }
            __half2 h0 = __floats2half2_rn(v0, v1);
            __half2 h1 = __floats2half2_rn(v2, v3);
            if (gr < Nrows)     *(__half2*)&Out[(size_t)gr * WBN + gc]       = h0;
            if (gr + 8 < Nrows) *(__half2*)&Out[(size_t)(gr + 8) * WBN + gc] = h1;
        }
    }
}

// ---------------------------------------------------------------------------
// Layer-3 GEMM (proven R7 kernel): BM=128 BN=128 BK=64, 3-stage, 256 threads.
constexpr int BM = 128, BN = 128, BKH = 64, NSTG = 3;
constexpr int STAGE_A = BM * BKH;
constexpr int STAGE_B = BN * BKH;
constexpr int MLP_SMEM = NSTG * (STAGE_A + STAGE_B) * 2;

__global__ void __launch_bounds__(256, 2) mlp_l3(const __half* __restrict__ In,
                                                 const __half* __restrict__ Wt,
                                                 const float* __restrict__ bias,
                                                 float* __restrict__ Out,
                                                 int Nrows, int K, int O) {
    extern __shared__ char smc[];
    __half* Abuf = (__half*)smc;
    __half* Bbuf = Abuf + NSTG * STAGE_A;
    int tid = threadIdx.x, lane = tid & 31, w = tid >> 5;
    int row0 = blockIdx.x * BM, col0 = 0;
    int kt = K / BKH;

    auto issue = [&](int s) {
        int buf = s % NSTG;
        uint32_t abase = smem_u32(Abuf + buf * STAGE_A);
        uint32_t bbase = smem_u32(Bbuf + buf * STAGE_B);
        int k0 = s * BKH;
#pragma unroll
        for (int i = 0; i < 4; i++) {
            int l = tid + i * 256;
            int r = l >> 3, u = l & 7;
            int gr = row0 + r;
            bool pa = gr < Nrows;
            const __half* srcA = pa ? (In + (size_t)gr * K + k0 + u * 8) : In;
            uint32_t da = abase + (uint32_t)((r * 8 + (u ^ (r & 7))) * 16);
            asm volatile("cp.async.ca.shared.global [%0], [%1], 16, %2;"
                         :: "r"(da), "l"(srcA), "r"(pa ? 16 : 0));
            const __half* srcB = Wt + (size_t)(col0 + r) * K + k0 + u * 8;
            uint32_t db = bbase + (uint32_t)((r * 8 + (u ^ (r & 7))) * 16);
            asm volatile("cp.async.ca.shared.global [%0], [%1], 16, %2;"
                         :: "r"(db), "l"(srcB), "r"(16));
        }
    };

    int wm = w & 1, wn = w >> 1;
    int arow0 = wm * 64 + (lane & 15);
    int brow0 = wn * 32 + (lane & 15);

    float d[4][4][4];
#pragma unroll
    for (int mi = 0; mi < 4; mi++)
#pragma unroll
        for (int ni = 0; ni < 4; ni++)
#pragma unroll
            for (int c = 0; c < 4; c++) d[mi][ni][c] = 0.f;

    issue(0);               asm volatile("cp.async.commit_group;");
    if (kt > 1) issue(1);   asm volatile("cp.async.commit_group;");

    for (int s = 0; s < kt; s++) {
        asm volatile("cp.async.wait_group %0;" :: "n"(1));
        __syncthreads();
        int buf = s % NSTG;
        uint32_t abase = smem_u32(Abuf + buf * STAGE_A);
        uint32_t bbase = smem_u32(Bbuf + buf * STAGE_B);
#pragma unroll
        for (int ks = 0; ks < 4; ks++) {
            int uu = ks * 2 + (lane >> 4);
            uint32_t a[4][4], b[2][4];
#pragma unroll
            for (int mi = 0; mi < 4; mi++) {
                int r = arow0 + mi * 16;
                ldsm4(a[mi], abase + (uint32_t)((r * 8 + (uu ^ (r & 7))) * 16));
            }
#pragma unroll
            for (int pp = 0; pp < 2; pp++) {
                int r = brow0 + pp * 16;
                ldsm4(b[pp], bbase + (uint32_t)((r * 8 + (uu ^ (r & 7))) * 16));
            }
#pragma unroll
            for (int mi = 0; mi < 4; mi++)
#pragma unroll
                for (int ni = 0; ni < 4; ni++) {
                    int pp = ni >> 1, o = ni & 1;
                    mma16(d[mi][ni], a[mi], b[pp][o], b[pp][2 + o]);
                }
        }
        if (s + 2 < kt) issue(s + 2);
        asm volatile("cp.async.commit_group;");
    }

#pragma unroll
    for (int ni = 0; ni < 4; ni++) {
        int gc = col0 + wn * 32 + ni * 8 + (lane & 3) * 2;
        float bj0 = bias[gc], bj1 = bias[gc + 1];
#pragma unroll
        for (int mi = 0; mi < 4; mi++) {
            int gr = row0 + wm * 64 + mi * 16 + (lane >> 2);
            float v0 = d[mi][ni][0] + bj0, v1 = d[mi][ni][1] + bj1;
            float v2 = d[mi][ni][2] + bj0, v3 = d[mi][ni][3] + bj1;
            if (gr < Nrows)     *(float2*)&Out[(size_t)gr * O + gc]       = make_float2(v0, v1);
            if (gr + 8 < Nrows) *(float2*)&Out[(size_t)(gr + 8) * O + gc] = make_float2(v2, v3);
        }
    }
}

// ---------------------------------------------------------------------------
extern "C" void kernel_launch(void* const* d_in, const int* in_sizes, int n_in,
                              void* d_out, int out_size) {
    const float* x     = (const float*)d_in[0];
    const int*   ei    = (const int*)d_in[1];
    const int*   et    = (const int*)d_in[2];
    const float* W     = (const float*)d_in[3];
    const float* eps   = (const float*)d_in[4];
    const float* A_emb = (const float*)d_in[5];
    const float* B_emb = (const float*)d_in[6];
    const float* W1    = (const float*)d_in[7];
    const float* b1    = (const float*)d_in[8];
    const float* W2    = (const float*)d_in[9];
    const float* b2    = (const float*)d_in[10];
    const float* W3    = (const float*)d_in[11];
    const float* b3    = (const float*)d_in[12];
    float* out = (float*)d_out;

    void *p_out, *p_xh, *p_h1, *p_h2, *p_w1, *p_w2, *p_w3;
    cudaGetSymbolAddress(&p_out, g_out);
    cudaGetSymbolAddress(&p_xh, g_xh);
    cudaGetSymbolAddress(&p_h1, g_h1);
    cudaGetSymbolAddress(&p_h2, g_h2);
    cudaGetSymbolAddress(&p_w1, g_W1h);
    cudaGetSymbolAddress(&p_w2, g_W2h);
    cudaGetSymbolAddress(&p_w3, g_W3h);

    cudaFuncSetAttribute(k_edge_mma, cudaFuncAttributeMaxDynamicSharedMemorySize, EDGE_SMEM);
    cudaFuncSetAttribute(mlp_wide<true, true>,  cudaFuncAttributeMaxDynamicSharedMemorySize, WIDE_SMEM);
    cudaFuncSetAttribute(mlp_wide<true, false>, cudaFuncAttributeMaxDynamicSharedMemorySize, WIDE_SMEM);
    cudaFuncSetAttribute(mlp_l3, cudaFuncAttributeMaxDynamicSharedMemorySize, MLP_SMEM);

    // launch index:                                            0
    k_prep<<<PREP_GRID, 256>>>(x, eps, W, A_emb, B_emb, W1, W2, W3, et);
    k_build_tiles<<<1, 256>>>();                             // 1
    k_scatter<<<(EE + 255) / 256, 256>>>(et);                // 2
    k_edge_mma<<<EDGE_GRID, 256, EDGE_SMEM>>>((const __half*)p_xh, ei);  // 3 <- profiled

    int gw = (NND + WBM - 1) / WBM;   // 1563
    mlp_wide<true, true><<<gw, 256, WIDE_SMEM>>>(p_out, (const __half*)p_w1, b1,
                                                 (__half*)p_h1, NND, DD);
    mlp_wide<true, false><<<gw, 256, WIDE_SMEM>>>(p_h1, (const __half*)p_w2, b2,
                                                  (__half*)p_h2, NND, H);
    int g3 = (NND + BM - 1) / BM;     // 782
    mlp_l3<<<g3, 256, MLP_SMEM>>>((const __half*)p_h2, (const __half*)p_w3, b3, out, NND, H, DD);
}

// round 10
// speedup vs baseline: 4.8894x; 1.0010x over previous
#include <cuda_runtime.h>
#include <cuda_fp16.h>
#include <cstdint>

constexpr int NND = 100000;
constexpr int DD  = 128;
constexpr int EE  = 250000;
constexpr int NRL = 16;
constexpr int RR  = 8;
constexpr int H   = 256;
constexpr int TE  = 64;
constexpr int CHUNK = 16;
constexpr int EDGE_GRID = 444;

// Static device scratch
__device__ __half g_Mh[NRL * DD * DD];
__device__ float  g_out[(size_t)NND * DD];
__device__ __half g_xh[(size_t)NND * DD];
__device__ __half g_h1[(size_t)NND * H];
__device__ __half g_h2[(size_t)NND * H];
__device__ __half g_W1h[H * DD];
__device__ __half g_W2h[H * H];
__device__ __half g_W3h[DD * H];
__device__ int    g_eidsb[(size_t)NRL * EE];   // per-relation edge-id buckets
__device__ int    g_fill[NRL];                  // bucket fill counts (zero-init; reset by mlp1)

// ---------------------------------------------------------------------------
__device__ __forceinline__ uint32_t smem_u32(const void* p) {
    return (uint32_t)__cvta_generic_to_shared(p);
}
__device__ __forceinline__ void ldsm4(uint32_t* r, uint32_t addr) {
    asm volatile("ldmatrix.sync.aligned.m8n8.x4.shared.b16 {%0,%1,%2,%3}, [%4];"
                 : "=r"(r[0]), "=r"(r[1]), "=r"(r[2]), "=r"(r[3]) : "r"(addr));
}
__device__ __forceinline__ void mma16(float* d, const uint32_t* a, uint32_t b0, uint32_t b1) {
    asm volatile(
        "mma.sync.aligned.m16n8k16.row.col.f32.f16.f16.f32 "
        "{%0,%1,%2,%3},{%4,%5,%6,%7},{%8,%9},{%0,%1,%2,%3};"
        : "+f"(d[0]), "+f"(d[1]), "+f"(d[2]), "+f"(d[3])
        : "r"(a[0]), "r"(a[1]), "r"(a[2]), "r"(a[3]), "r"(b0), "r"(b1));
}
__device__ __forceinline__ void pack8h(uint32_t* o, const float* f) {
#pragma unroll
    for (int i = 0; i < 4; i++) {
        __half2 h = __floats2half2_rn(f[2 * i], f[2 * i + 1]);
        o[i] = *(uint32_t*)&h;
    }
}

// ---------------------------------------------------------------------------
// Bucketed scatter: block-aggregated atomics, writes edge ids into
// g_eidsb[t*EE + pos]. No histogram / offset pass needed.
__global__ void k_scatter(const int* __restrict__ et) {
    __shared__ int lc[NRL], lbase[NRL], lfill[NRL];
    if (threadIdx.x < NRL) { lc[threadIdx.x] = 0; lfill[threadIdx.x] = 0; }
    __syncthreads();
    int e = blockIdx.x * blockDim.x + threadIdx.x;
    int t = -1;
    if (e < EE) {
        t = et[e];
        if (t >= 0 && t < NRL) atomicAdd(&lc[t], 1); else t = -1;
    }
    __syncthreads();
    if (threadIdx.x < NRL && lc[threadIdx.x])
        lbase[threadIdx.x] = atomicAdd(&g_fill[threadIdx.x], lc[threadIdx.x]);
    __syncthreads();
    if (t >= 0) {
        int p = atomicAdd(&lfill[t], 1);
        g_eidsb[(size_t)t * EE + lbase[t] + p] = e;
    }
}

// ---------------------------------------------------------------------------
// Fused prep: [0,16) build_M, [16,12516) init_out+cvt_x, [12516,12772) cvt_w.
constexpr int PREP_INIT0 = NRL;                       // 16
constexpr int PREP_CVTW0 = PREP_INIT0 + 12500;        // 12516
constexpr int PREP_GRID  = PREP_CVTW0 + 256;          // 12772

__global__ void __launch_bounds__(256) k_prep(const float* __restrict__ x,
                                              const float* __restrict__ eps,
                                              const float* __restrict__ W,
                                              const float* __restrict__ A_emb,
                                              const float* __restrict__ B_emb,
                                              const float* __restrict__ W1,
                                              const float* __restrict__ W2,
                                              const float* __restrict__ W3) {
    int b = blockIdx.x;
    if (b < PREP_INIT0) {
        int t = b;
        __shared__ float As[DD * RR];
        __shared__ float Bs[DD * RR];
        for (int i = threadIdx.x; i < DD * RR; i += blockDim.x) {
            As[i] = A_emb[(size_t)t * DD * RR + i];
            Bs[i] = B_emb[(size_t)t * DD * RR + i];
        }
        __syncthreads();
        for (int idx = threadIdx.x; idx < DD * DD; idx += blockDim.x) {
            int o = idx >> 7;
            int i = idx & 127;
            float s = W[o * DD + i];
#pragma unroll
            for (int k = 0; k < RR; k++) s += Bs[i * RR + k] * As[o * RR + k];
            g_Mh[t * DD * DD + o * DD + i] = __float2half_rn(s);
        }
    } else if (b < PREP_CVTW0) {
        float s = 1.0f + eps[0];
        int i = (b - PREP_INIT0) * 256 + threadIdx.x;
        if (i < NND * DD / 4) {
            float4 v = ((const float4*)x)[i];
            __half2 h0 = __floats2half2_rn(v.x, v.y);
            __half2 h1 = __floats2half2_rn(v.z, v.w);
            uint2 u; u.x = *(uint32_t*)&h0; u.y = *(uint32_t*)&h1;
            ((uint2*)g_xh)[i] = u;
            v.x *= s; v.y *= s; v.z *= s; v.w *= s;
            ((float4*)g_out)[i] = v;
        }
    } else {
        int i = (b - PREP_CVTW0) * 256 + threadIdx.x;
        if (i < H * DD) g_W1h[i] = __float2half_rn(W1[i]);
        if (i < H * H)  g_W2h[i] = __float2half_rn(W2[i]);
        if (i < DD * H) g_W3h[i] = __float2half_rn(W3[i]);
    }
}

// ---------------------------------------------------------------------------
// Persistent edge GEMM: tile table derived on the fly from bucket counts.
constexpr int EDGE_SMEM = 32768 + 32768 + CHUNK * TE * 2 * 4;   // 73728

__global__ void __launch_bounds__(256, 3) k_edge_mma(const __half* __restrict__ xh,
                                                     const int* __restrict__ ei) {
    extern __shared__ char smc[];
    __half* Ms = (__half*)smc;                   // 32KB
    char* Xb = smc + 32768;                      // 2x16KB
    int* srcsA = (int*)(smc + 65536);            // CHUNK*64
    int* dstsA = srcsA + CHUNK * TE;
    __shared__ int s_cnt[NRL];
    __shared__ int s_tstart[NRL + 1];
    __shared__ int s_trel[CHUNK];
    int tid = threadIdx.x;

    if (tid < NRL) s_cnt[tid] = g_fill[tid];
    __syncthreads();
    if (tid == 0) {
        int tb = 0;
        for (int t = 0; t < NRL; t++) { s_tstart[t] = tb; tb += (s_cnt[t] + TE - 1) / TE; }
        s_tstart[NRL] = tb;
    }
    __syncthreads();
    int nt = s_tstart[NRL];

    int per = (nt + gridDim.x - 1) / gridDim.x;
    int i0 = blockIdx.x * per;
    int i1 = min(i0 + per, nt);
    if (i0 >= i1) return;

    int lane = tid & 31, w = tid >> 5;
    int wm = w & 1, wn = w >> 1;
    int arow0 = wm * 32 + (lane & 15);
    int brow0 = wn * 32 + (lane & 15);
    uint32_t ms_base = smem_u32(Ms);
    int cur_rel = -1;

    auto gather = [&](int k) {
        char* xb = Xb + (k & 1) * 16384;
        const int* sp = srcsA + k * TE;
        uint32_t xb32 = smem_u32(xb);
#pragma unroll
        for (int i = 0; i < 4; i++) {
            int l = tid + i * 256;
            int r = l >> 4, u = l & 15;
            int s = sp[r];
            bool pa = s >= 0;
            const __half* src = pa ? (xh + (size_t)s * DD + u * 8) : xh;
            uint32_t dst = xb32 + (uint32_t)((r * 16 + (u ^ (r & 7))) * 16);
            asm volatile("cp.async.ca.shared.global [%0], [%1], 16, %2;"
                         :: "r"(dst), "l"(src), "r"(pa ? 16 : 0));
        }
        asm volatile("cp.async.commit_group;");
    };

    for (int gbase = i0; gbase < i1; gbase += CHUNK) {
        int gc = min(CHUNK, i1 - gbase);

        // per-tile relation lookup for this group
        if (tid < gc) {
            int ti = gbase + tid;
            int t = 0;
            for (int tt = 0; tt < NRL; tt++)
                if (ti >= s_tstart[tt] && ti < s_tstart[tt + 1]) t = tt;
            s_trel[tid] = t;
        }
        __syncthreads();

        // batched index preload
        for (int l = tid; l < gc * TE; l += 256) {
            int k = l >> 6, j = l & 63;
            int t = s_trel[k];
            int row0 = (gbase + k - s_tstart[t]) * TE;
            int cnt = s_cnt[t] - row0;
            int s = -1, d = -1;
            if (j < cnt) {
                int e = g_eidsb[(size_t)t * EE + row0 + j];
                s = ei[e];
                d = ei[EE + e];
                if (s < 0 || s >= NND) s = -1;
                if (d < 0 || d >= NND) d = -1;
            }
            srcsA[l] = s;
            dstsA[l] = d;
        }
        __syncthreads();

        gather(0);
        for (int k = 0; k < gc; k++) {
            if (k + 1 < gc) {
                gather(k + 1);
                asm volatile("cp.async.wait_group 1;");
            } else {
                asm volatile("cp.async.wait_group 0;");
            }
            __syncthreads();

            int t = s_trel[k];
            if (t != cur_rel) {
                const uint4* Msrc = (const uint4*)(g_Mh + (size_t)t * DD * DD);
#pragma unroll
                for (int j = 0; j < 8; j++) {
                    int l = tid + j * 256;
                    int r = l >> 4, u = l & 15;
                    uint4 v = Msrc[l];
                    *(uint4*)((char*)Ms + (r * 16 + (u ^ (r & 7))) * 16) = v;
                }
                cur_rel = t;
                __syncthreads();
            }

            uint32_t xs_base = smem_u32(Xb + (k & 1) * 16384);
            float d[2][4][4];
#pragma unroll
            for (int mi = 0; mi < 2; mi++)
#pragma unroll
                for (int ni = 0; ni < 4; ni++)
#pragma unroll
                    for (int c = 0; c < 4; c++) d[mi][ni][c] = 0.f;

#pragma unroll
            for (int ks = 0; ks < 8; ks++) {
                int uu = ks * 2 + (lane >> 4);
                uint32_t a[2][4], b[2][4];
#pragma unroll
                for (int mi = 0; mi < 2; mi++) {
                    int r = arow0 + mi * 16;
                    ldsm4(a[mi], xs_base + (uint32_t)((r * 16 + (uu ^ (r & 7))) * 16));
                }
#pragma unroll
                for (int pp = 0; pp < 2; pp++) {
                    int r = brow0 + pp * 16;
                    ldsm4(b[pp], ms_base + (uint32_t)((r * 16 + (uu ^ (r & 7))) * 16));
                }
#pragma unroll
                for (int mi = 0; mi < 2; mi++)
#pragma unroll
                    for (int ni = 0; ni < 4; ni++) {
                        int pp = ni >> 1, o = ni & 1;
                        mma16(d[mi][ni], a[mi], b[pp][o], b[pp][2 + o]);
                    }
            }

            const int* dp = dstsA + k * TE;
            int ocb = wn * 32 + (lane & 3) * 2;
#pragma unroll
            for (int mi = 0; mi < 2; mi++) {
                int er = wm * 32 + mi * 16 + (lane >> 2);
                int d0 = dp[er];
                int d1 = dp[er + 8];
#pragma unroll
                for (int ni = 0; ni < 4; ni++) {
                    int oc = ocb + ni * 8;
                    if (d0 >= 0) {
                        float* p = g_out + (size_t)d0 * DD + oc;
                        asm volatile("red.global.add.v2.f32 [%0], {%1,%2};"
                                     :: "l"(p), "f"(d[mi][ni][0]), "f"(d[mi][ni][1]) : "memory");
                    }
                    if (d1 >= 0) {
                        float* p = g_out + (size_t)d1 * DD + oc;
                        asm volatile("red.global.add.v2.f32 [%0], {%1,%2};"
                                     :: "l"(p), "f"(d[mi][ni][2]), "f"(d[mi][ni][3]) : "memory");
                    }
                }
            }
            __syncthreads();
        }
    }
}

// ---------------------------------------------------------------------------
// Wide MLP GEMM (layers 1-2): BM=64, BN=256, BK=64, double-buffered,
// 256 threads, warp tile 32x64, 2 CTAs/SM. Layer 1 also resets g_fill.
constexpr int WBM = 64, WBN = 256, WBK = 64;
constexpr int WSA = WBM * WBK;
constexpr int WSB = WBN * WBK;
constexpr int WIDE_SMEM = 2 * (WSA + WSB) * 2;   // 81920

template <bool RELU, bool IN_FLOAT>
__global__ void __launch_bounds__(256, 2) mlp_wide(const void* __restrict__ InV,
                                                   const __half* __restrict__ Wt,
                                                   const float* __restrict__ bias,
                                                   __half* __restrict__ Out,
                                                   int Nrows, int K) {
    extern __shared__ char smc[];
    __half* Abuf = (__half*)smc;
    __half* Bbuf = Abuf + 2 * WSA;
    int tid = threadIdx.x, lane = tid & 31, w = tid >> 5;
    int row0 = blockIdx.x * WBM;
    int kt = K / WBK;

    if (IN_FLOAT && blockIdx.x < NRL && tid == 0) g_fill[blockIdx.x] = 0;  // reset for replay

    auto issue = [&](int s) {
        int buf = s & 1;
        uint32_t bbase = smem_u32(Bbuf + buf * WSB);
        int k0 = s * WBK;
#pragma unroll
        for (int i = 0; i < 2; i++) {
            int l = tid + i * 256;
            int r = l >> 3, u = l & 7;
            int gr = row0 + r;
            bool pa = gr < Nrows;
            if (IN_FLOAT) {
                const float* In = (const float*)InV;
                float f[8];
                if (pa) {
                    const float4* src = (const float4*)(In + (size_t)gr * K + k0 + u * 8);
                    float4 a = src[0], b = src[1];
                    f[0]=a.x; f[1]=a.y; f[2]=a.z; f[3]=a.w;
                    f[4]=b.x; f[5]=b.y; f[6]=b.z; f[7]=b.w;
                } else {
#pragma unroll
                    for (int q = 0; q < 8; q++) f[q] = 0.f;
                }
                uint32_t h[4];
                pack8h(h, f);
                *(uint4*)(Abuf + buf * WSA + (r * 8 + (u ^ (r & 7))) * 8) =
                    make_uint4(h[0], h[1], h[2], h[3]);
            } else {
                const __half* In = (const __half*)InV;
                const __half* src = pa ? (In + (size_t)gr * K + k0 + u * 8) : In;
                uint32_t dst = smem_u32(Abuf + buf * WSA) +
                               (uint32_t)((r * 8 + (u ^ (r & 7))) * 16);
                asm volatile("cp.async.ca.shared.global [%0], [%1], 16, %2;"
                             :: "r"(dst), "l"(src), "r"(pa ? 16 : 0));
            }
        }
#pragma unroll
        for (int i = 0; i < 8; i++) {
            int l = tid + i * 256;
            int r = l >> 3, u = l & 7;
            const __half* src = Wt + (size_t)r * K + k0 + u * 8;
            uint32_t dst = bbase + (uint32_t)((r * 8 + (u ^ (r & 7))) * 16);
            asm volatile("cp.async.ca.shared.global [%0], [%1], 16, %2;"
                         :: "r"(dst), "l"(src), "r"(16));
        }
        asm volatile("cp.async.commit_group;");
    };

    int wm = w & 1, wn = w >> 1;
    int arow0 = wm * 32 + (lane & 15);
    int brow0 = wn * 64 + (lane & 15);

    float d[2][8][4];
#pragma unroll
    for (int mi = 0; mi < 2; mi++)
#pragma unroll
        for (int nj = 0; nj < 8; nj++)
#pragma unroll
            for (int c = 0; c < 4; c++) d[mi][nj][c] = 0.f;

    issue(0);

    for (int s = 0; s < kt; s++) {
        asm volatile("cp.async.wait_group 0;");
        __syncthreads();
        if (s + 1 < kt) issue(s + 1);
        int buf = s & 1;
        uint32_t abase = smem_u32(Abuf + buf * WSA);
        uint32_t bbase = smem_u32(Bbuf + buf * WSB);
#pragma unroll
        for (int ks = 0; ks < 4; ks++) {
            int uu = ks * 2 + (lane >> 4);
            uint32_t a[2][4], b[4][4];
#pragma unroll
            for (int mi = 0; mi < 2; mi++) {
                int r = arow0 + mi * 16;
                ldsm4(a[mi], abase + (uint32_t)((r * 8 + (uu ^ (r & 7))) * 16));
            }
#pragma unroll
            for (int pp = 0; pp < 4; pp++) {
                int r = brow0 + pp * 16;
                ldsm4(b[pp], bbase + (uint32_t)((r * 8 + (uu ^ (r & 7))) * 16));
            }
#pragma unroll
            for (int mi = 0; mi < 2; mi++)
#pragma unroll
                for (int nj = 0; nj < 8; nj++) {
                    int pp = nj >> 1, o = nj & 1;
                    mma16(d[mi][nj], a[mi], b[pp][o], b[pp][2 + o]);
                }
        }
    }

#pragma unroll
    for (int nj = 0; nj < 8; nj++) {
        int gc = wn * 64 + nj * 8 + (lane & 3) * 2;
        float bj0 = bias[gc], bj1 = bias[gc + 1];
#pragma unroll
        for (int mi = 0; mi < 2; mi++) {
            int gr = row0 + wm * 32 + mi * 16 + (lane >> 2);
            float v0 = d[mi][nj][0] + bj0, v1 = d[mi][nj][1] + bj1;
            float v2 = d[mi][nj][2] + bj0, v3 = d[mi][nj][3] + bj1;
            if (RELU) {
                v0 = fmaxf(v0, 0.f); v1 = fmaxf(v1, 0.f);
                v2 = fmaxf(v2, 0.f); v3 = fmaxf(v3, 0.f);
            }
            __half2 h0 = __floats2half2_rn(v0, v1);
            __half2 h1 = __floats2half2_rn(v2, v3);
            if (gr < Nrows)     *(__half2*)&Out[(size_t)gr * WBN + gc]       = h0;
            if (gr + 8 < Nrows) *(__half2*)&Out[(size_t)(gr + 8) * WBN + gc] = h1;
        }
    }
}

// ---------------------------------------------------------------------------
// Layer-3 GEMM: BM=128 BN=128 BK=64, 3-stage, 256 threads.
constexpr int BM = 128, BN = 128, BKH = 64, NSTG = 3;
constexpr int STAGE_A = BM * BKH;
constexpr int STAGE_B = BN * BKH;
constexpr int MLP_SMEM = NSTG * (STAGE_A + STAGE_B) * 2;

__global__ void __launch_bounds__(256, 2) mlp_l3(const __half* __restrict__ In,
                                                 const __half* __restrict__ Wt,
                                                 const float* __restrict__ bias,
                                                 float* __restrict__ Out,
                                                 int Nrows, int K, int O) {
    extern __shared__ char smc[];
    __half* Abuf = (__half*)smc;
    __half* Bbuf = Abuf + NSTG * STAGE_A;
    int tid = threadIdx.x, lane = tid & 31, w = tid >> 5;
    int row0 = blockIdx.x * BM;
    int kt = K / BKH;

    auto issue = [&](int s) {
        int buf = s % NSTG;
        uint32_t abase = smem_u32(Abuf + buf * STAGE_A);
        uint32_t bbase = smem_u32(Bbuf + buf * STAGE_B);
        int k0 = s * BKH;
#pragma unroll
        for (int i = 0; i < 4; i++) {
            int l = tid + i * 256;
            int r = l >> 3, u = l & 7;
            int gr = row0 + r;
            bool pa = gr < Nrows;
            const __half* srcA = pa ? (In + (size_t)gr * K + k0 + u * 8) : In;
            uint32_t da = abase + (uint32_t)((r * 8 + (u ^ (r & 7))) * 16);
            asm volatile("cp.async.ca.shared.global [%0], [%1], 16, %2;"
                         :: "r"(da), "l"(srcA), "r"(pa ? 16 : 0));
            const __half* srcB = Wt + (size_t)r * K + k0 + u * 8;
            uint32_t db = bbase + (uint32_t)((r * 8 + (u ^ (r & 7))) * 16);
            asm volatile("cp.async.ca.shared.global [%0], [%1], 16, %2;"
                         :: "r"(db), "l"(srcB), "r"(16));
        }
    };

    int wm = w & 1, wn = w >> 1;
    int arow0 = wm * 64 + (lane & 15);
    int brow0 = wn * 32 + (lane & 15);

    float d[4][4][4];
#pragma unroll
    for (int mi = 0; mi < 4; mi++)
#pragma unroll
        for (int ni = 0; ni < 4; ni++)
#pragma unroll
            for (int c = 0; c < 4; c++) d[mi][ni][c] = 0.f;

    issue(0);               asm volatile("cp.async.commit_group;");
    if (kt > 1) issue(1);   asm volatile("cp.async.commit_group;");

    for (int s = 0; s < kt; s++) {
        asm volatile("cp.async.wait_group %0;" :: "n"(1));
        __syncthreads();
        int buf = s % NSTG;
        uint32_t abase = smem_u32(Abuf + buf * STAGE_A);
        uint32_t bbase = smem_u32(Bbuf + buf * STAGE_B);
#pragma unroll
        for (int ks = 0; ks < 4; ks++) {
            int uu = ks * 2 + (lane >> 4);
            uint32_t a[4][4], b[2][4];
#pragma unroll
            for (int mi = 0; mi < 4; mi++) {
                int r = arow0 + mi * 16;
                ldsm4(a[mi], abase + (uint32_t)((r * 8 + (uu ^ (r & 7))) * 16));
            }
#pragma unroll
            for (int pp = 0; pp < 2; pp++) {
                int r = brow0 + pp * 16;
                ldsm4(b[pp], bbase + (uint32_t)((r * 8 + (uu ^ (r & 7))) * 16));
            }
#pragma unroll
            for (int mi = 0; mi < 4; mi++)
#pragma unroll
                for (int ni = 0; ni < 4; ni++) {
                    int pp = ni >> 1, o = ni & 1;
                    mma16(d[mi][ni], a[mi], b[pp][o], b[pp][2 + o]);
                }
        }
        if (s + 2 < kt) issue(s + 2);
        asm volatile("cp.async.commit_group;");
    }

#pragma unroll
    for (int ni = 0; ni < 4; ni++) {
        int gc = wn * 32 + ni * 8 + (lane & 3) * 2;
        float bj0 = bias[gc], bj1 = bias[gc + 1];
#pragma unroll
        for (int mi = 0; mi < 4; mi++) {
            int gr = row0 + wm * 64 + mi * 16 + (lane >> 2);
            float v0 = d[mi][ni][0] + bj0, v1 = d[mi][ni][1] + bj1;
            float v2 = d[mi][ni][2] + bj0, v3 = d[mi][ni][3] + bj1;
            if (gr < Nrows)     *(float2*)&Out[(size_t)gr * O + gc]       = make_float2(v0, v1);
            if (gr + 8 < Nrows) *(float2*)&Out[(size_t)(gr + 8) * O + gc] = make_float2(v2, v3);
        }
    }
}

// ---------------------------------------------------------------------------
extern "C" void kernel_launch(void* const* d_in, const int* in_sizes, int n_in,
                              void* d_out, int out_size) {
    const float* x     = (const float*)d_in[0];
    const int*   ei    = (const int*)d_in[1];
    const int*   et    = (const int*)d_in[2];
    const float* W     = (const float*)d_in[3];
    const float* eps   = (const float*)d_in[4];
    const float* A_emb = (const float*)d_in[5];
    const float* B_emb = (const float*)d_in[6];
    const float* W1    = (const float*)d_in[7];
    const float* b1    = (const float*)d_in[8];
    const float* W2    = (const float*)d_in[9];
    const float* b2    = (const float*)d_in[10];
    const float* W3    = (const float*)d_in[11];
    const float* b3    = (const float*)d_in[12];
    float* out = (float*)d_out;

    void *p_out, *p_xh, *p_h1, *p_h2, *p_w1, *p_w2, *p_w3;
    cudaGetSymbolAddress(&p_out, g_out);
    cudaGetSymbolAddress(&p_xh, g_xh);
    cudaGetSymbolAddress(&p_h1, g_h1);
    cudaGetSymbolAddress(&p_h2, g_h2);
    cudaGetSymbolAddress(&p_w1, g_W1h);
    cudaGetSymbolAddress(&p_w2, g_W2h);
    cudaGetSymbolAddress(&p_w3, g_W3h);

    cudaFuncSetAttribute(k_edge_mma, cudaFuncAttributeMaxDynamicSharedMemorySize, EDGE_SMEM);
    cudaFuncSetAttribute(mlp_wide<true, true>,  cudaFuncAttributeMaxDynamicSharedMemorySize, WIDE_SMEM);
    cudaFuncSetAttribute(mlp_wide<true, false>, cudaFuncAttributeMaxDynamicSharedMemorySize, WIDE_SMEM);
    cudaFuncSetAttribute(mlp_l3, cudaFuncAttributeMaxDynamicSharedMemorySize, MLP_SMEM);

    // launch index:
    k_scatter<<<(EE + 255) / 256, 256>>>(et);                            // 0
    k_prep<<<PREP_GRID, 256>>>(x, eps, W, A_emb, B_emb, W1, W2, W3);     // 1
    k_edge_mma<<<EDGE_GRID, 256, EDGE_SMEM>>>((const __half*)p_xh, ei);  // 2

    int gw = (NND + WBM - 1) / WBM;   // 1563
    mlp_wide<true, true><<<gw, 256, WIDE_SMEM>>>(p_out, (const __half*)p_w1, b1,
                                                 (__half*)p_h1, NND, DD);            // 3 <- profiled
    mlp_wide<true, false><<<gw, 256, WIDE_SMEM>>>(p_h1, (const __half*)p_w2, b2,
                                                  (__half*)p_h2, NND, H);            // 4
    int g3 = (NND + BM - 1) / BM;     // 782
    mlp_l3<<<g3, 256, MLP_SMEM>>>((const __half*)p_h2, (const __half*)p_w3, b3, out, NND, H, DD);  // 5
}